// round 6
// baseline (speedup 1.0000x reference)
#include <cuda_runtime.h>
#include <cuda_fp16.h>
#include <cstdint>
#include <cstddef>

// ---------------------------------------------------------------------------
// Sigmoid attention via 5 fp16 mma.sync.m16n8k16 GEMMs (legacy HMMA path;
// tcgen05 unavailable: harness compiles through virtual arch compute_100).
// R6 = R5 resubmit (R5 bench was an infra container failure, no kernel signal):
// CTA tile 128x256 (8 warps, 64x64 each), 4-stage cp.async pipeline, 1 CTA/SM.
//   qT[n,o]  = xT[n,c]*Wq[o,c] + bq[o]
//   kT[m,o]  = xT[m,c]*Wk[o,c] + bk[o]
//   v[c,n]   = Wv[c,c']*xT[n,c'] + bv[c]
//   aT[m,n]  = sigmoid(kT[m,o]*qT[n,o])
//   out[c,m] = v[c,n]*aT[m,n]
// All GEMMs: D[m,n] = sum_k A[m,k]*B[n,k], A/B K-contiguous fp16, fp32 accum.
// ---------------------------------------------------------------------------

#define BM 128
#define BN 256
#define BKH 64                    // K halves per chunk (128 B per row)
#define A_BYTES (BM * 128)        // 16 KB
#define B_BYTES (BN * 128)        // 32 KB
#define STAGE (A_BYTES + B_BYTES) // 48 KB
#define NSTAGE 4
#define SMEM_TOTAL (NSTAGE * STAGE)   // 192 KB

// ------------------------------- scratch ------------------------------------
#define AL16 __align__(16)
static __device__ AL16 __half g_xT [(size_t)4*4096*512];    // xT[b][n][c]
static __device__ AL16 __half g_Wq [1024*512];              // rows padded 1000->1024
static __device__ AL16 __half g_Wk [1024*512];
static __device__ AL16 __half g_Wv [512*512];
static __device__ float g_bq[1024], g_bk[1024], g_bv[512];
static __device__ AL16 __half g_q  [(size_t)4*4096*1024];   // qT[b][n][o]
static __device__ AL16 __half g_k  [(size_t)4*4096*1024];   // kT[b][m][o]
static __device__ AL16 __half g_v  [(size_t)4*512*4096];    // v[b][c][n]
static __device__ AL16 __half g_a  [(size_t)4*4096*4096];   // aT[b][m][n]

// ------------------------------- helpers ------------------------------------
__device__ __forceinline__ void ldsm_x4(uint32_t& r0, uint32_t& r1, uint32_t& r2, uint32_t& r3,
                                        uint32_t addr) {
    asm volatile("ldmatrix.sync.aligned.m8n8.x4.shared.b16 {%0,%1,%2,%3}, [%4];"
                 : "=r"(r0), "=r"(r1), "=r"(r2), "=r"(r3) : "r"(addr));
}

__device__ __forceinline__ void mma_fp16(float* d, const uint32_t* a, const uint32_t* b) {
    asm volatile(
        "mma.sync.aligned.m16n8k16.row.col.f32.f16.f16.f32 "
        "{%0,%1,%2,%3}, {%4,%5,%6,%7}, {%8,%9}, {%0,%1,%2,%3};\n"
        : "+f"(d[0]), "+f"(d[1]), "+f"(d[2]), "+f"(d[3])
        : "r"(a[0]), "r"(a[1]), "r"(a[2]), "r"(a[3]), "r"(b[0]), "r"(b[1]));
}

// ---------------------------- prep kernels ----------------------------------
// x[b][c][n] fp32 -> xT[b][n][c] fp16
__global__ void xpose_h(const float* __restrict__ x, __half* __restrict__ xT) {
    __shared__ float t[32][33];
    const int b = blockIdx.z;
    const float* xb = x + (size_t)b * 512 * 4096;
    const int n0 = blockIdx.x * 32, c0 = blockIdx.y * 32;
    const int tx = threadIdx.x, ty0 = threadIdx.y;
#pragma unroll
    for (int i = 0; i < 4; i++) {
        int ty = ty0 + i * 8;
        t[ty][tx] = xb[(size_t)(c0 + ty) * 4096 + n0 + tx];
    }
    __syncthreads();
    const size_t ob = (size_t)b * 4096 * 512;
#pragma unroll
    for (int i = 0; i < 4; i++) {
        int ty = ty0 + i * 8;
        xT[ob + (size_t)(n0 + ty) * 512 + c0 + tx] = __float2half_rn(t[tx][ty]);
    }
}

// W[Mvalid][K] fp32 -> fp16 [Mout][K] zero-padded; bias padded
__global__ void conv_pad_w(const float* __restrict__ W, const float* __restrict__ b,
                           __half* __restrict__ Wh, float* __restrict__ bp,
                           int Mout, int Mvalid, int Kd) {
    int idx = blockIdx.x * blockDim.x + threadIdx.x;
    if (idx < Mout * Kd) {
        int m = idx / Kd;
        Wh[idx] = __float2half_rn((m < Mvalid) ? W[idx] : 0.0f);
    }
    if (idx < Mout) bp[idx] = (idx < Mvalid) ? b[idx] : 0.0f;
}

// ------------------------------- GEMM ---------------------------------------
// EPI: 0 = fp32 store ; 1 = +bias[col] -> fp16 ; 2 = +bias[row] -> fp16 ; 3 = sigmoid -> fp16
template <int EPI>
__global__ __launch_bounds__(256, 1)
void gemm_h(const __half* __restrict__ Ag, size_t sA,
            const __half* __restrict__ Bg, size_t sB,
            void* Dg, size_t sD,
            const float* __restrict__ bias,
            int Ntot, int K) {
    extern __shared__ __align__(1024) char smem[];
    const uint32_t sb = (uint32_t)__cvta_generic_to_shared(smem);

    const __half* A = Ag + (size_t)blockIdx.z * sA;
    const __half* B = Bg + (size_t)blockIdx.z * sB;
    const int m0 = blockIdx.y * BM;
    const int n0 = blockIdx.x * BN;
    const int tid  = threadIdx.x;
    const int lane = tid & 31;
    const int w    = tid >> 5;
    const int wm   = (w & 1) * 64;          // 2 warps over M
    const int wn   = (w >> 1) * 64;         // 4 warps over N
    const int g    = lane >> 2;
    const int tg   = lane & 3;

    const int T = K / BKH;

    auto load_stage = [&](int t, int s) {
        const uint32_t st = sb + (uint32_t)(s * STAGE);
        const int kc = t * BKH;
#pragma unroll
        for (int i = 0; i < 12; i++) {
            int idx = tid + i * 256;            // 0..3071 : A first 1024, B next 2048
            int isB = (idx >= 1024);
            int rel = isB ? (idx - 1024) : idx;
            int r   = rel >> 3;                 // A row 0..127 / B row 0..255
            int c   = rel & 7;                  // 16B chunk
            uint32_t dst = st + (uint32_t)(isB * A_BYTES + r * 128 + ((c ^ (r & 7)) << 4));
            const __half* gp = (isB ? B + (size_t)(n0 + r) * K
                                    : A + (size_t)(m0 + r) * K) + kc + c * 8;
            asm volatile("cp.async.cg.shared.global [%0], [%1], 16;" :: "r"(dst), "l"(gp) : "memory");
        }
        asm volatile("cp.async.commit_group;" ::: "memory");
    };

    float acc[4][8][4];
#pragma unroll
    for (int i = 0; i < 4; i++)
#pragma unroll
        for (int j = 0; j < 8; j++)
#pragma unroll
            for (int r = 0; r < 4; r++) acc[i][j][r] = 0.0f;

    load_stage(0, 0);
    if (T > 1) load_stage(1, 1);
    if (T > 2) load_stage(2, 2);

    // ldmatrix lane addressing
    const int rowA = wm + (lane & 15);                        // + im*16
    const int hiA  = lane >> 4;                               // k8 chunk +0/+1
    const int rowB = wn + ((lane >> 4) << 3) + (lane & 7);    // + jn*16
    const int hiB  = (lane >> 3) & 1;

    for (int t = 0; t < T; t++) {
        // wait until stage t is resident (pending groups: t .. min(T-1, t+2))
        if (t + 2 < T)      asm volatile("cp.async.wait_group 2;" ::: "memory");
        else if (t + 1 < T) asm volatile("cp.async.wait_group 1;" ::: "memory");
        else                asm volatile("cp.async.wait_group 0;" ::: "memory");
        __syncthreads();
        if (t + 3 < T) load_stage(t + 3, (t + 3) & (NSTAGE - 1));

        const uint32_t st  = sb + (uint32_t)((t & (NSTAGE - 1)) * STAGE);
        const uint32_t stB = st + A_BYTES;
#pragma unroll
        for (int ks = 0; ks < 4; ks++) {
            uint32_t af[4][4], bf[8][2];
#pragma unroll
            for (int im = 0; im < 4; im++) {
                const int r = rowA + im * 16;
                const int c = (ks * 2 + hiA) ^ (r & 7);
                ldsm_x4(af[im][0], af[im][1], af[im][2], af[im][3],
                        st + (uint32_t)(r * 128 + (c << 4)));
            }
#pragma unroll
            for (int jn = 0; jn < 4; jn++) {
                const int r = rowB + jn * 16;
                const int c = (ks * 2 + hiB) ^ (r & 7);
                ldsm_x4(bf[2*jn][0], bf[2*jn][1], bf[2*jn+1][0], bf[2*jn+1][1],
                        stB + (uint32_t)(r * 128 + (c << 4)));
            }
#pragma unroll
            for (int im = 0; im < 4; im++)
#pragma unroll
                for (int in = 0; in < 8; in++)
                    mma_fp16(acc[im][in], af[im], bf[in]);
        }
    }

    // ------------------------------ epilogue ---------------------------------
#pragma unroll
    for (int im = 0; im < 4; im++) {
        const int r0 = m0 + wm + im * 16 + g;
#pragma unroll
        for (int in = 0; in < 8; in++) {
            const int c = n0 + wn + in * 8 + 2 * tg;
#pragma unroll
            for (int h = 0; h < 2; h++) {
                const int r = r0 + h * 8;
                float vx = acc[im][in][2 * h];
                float vy = acc[im][in][2 * h + 1];
                if (EPI == 1) { vx += bias[c]; vy += bias[c + 1]; }
                if (EPI == 2) { float bb = bias[r]; vx += bb; vy += bb; }
                if (EPI == 3) {
                    vx = __fdividef(1.0f, 1.0f + __expf(-vx));
                    vy = __fdividef(1.0f, 1.0f + __expf(-vy));
                }
                if (EPI == 0) {
                    float* D = (float*)Dg + (size_t)blockIdx.z * sD + (size_t)r * Ntot + c;
                    *reinterpret_cast<float2*>(D) = make_float2(vx, vy);
                } else {
                    __half* D = (__half*)Dg + (size_t)blockIdx.z * sD + (size_t)r * Ntot + c;
                    *reinterpret_cast<__half2*>(D) = __floats2half2_rn(vx, vy);
                }
            }
        }
    }
}

// ------------------------------- launch -------------------------------------
extern "C" void kernel_launch(void* const* d_in, const int* in_sizes, int n_in,
                              void* d_out, int out_size) {
    (void)in_sizes; (void)n_in; (void)out_size;
    const float* x  = (const float*)d_in[0];
    const float* Wq = (const float*)d_in[1];
    const float* bq = (const float*)d_in[2];
    const float* Wk = (const float*)d_in[3];
    const float* bk = (const float*)d_in[4];
    const float* Wv = (const float*)d_in[5];
    const float* bv = (const float*)d_in[6];
    float* out = (float*)d_out;

    __half *xT,*Wqh,*Wkh,*Wvh,*q,*k,*v,*a;
    float *bqp,*bkp,*bvp;
    cudaGetSymbolAddress((void**)&xT,  g_xT);
    cudaGetSymbolAddress((void**)&Wqh, g_Wq);
    cudaGetSymbolAddress((void**)&Wkh, g_Wk);
    cudaGetSymbolAddress((void**)&Wvh, g_Wv);
    cudaGetSymbolAddress((void**)&bqp, g_bq);
    cudaGetSymbolAddress((void**)&bkp, g_bk);
    cudaGetSymbolAddress((void**)&bvp, g_bv);
    cudaGetSymbolAddress((void**)&q,   g_q);
    cudaGetSymbolAddress((void**)&k,   g_k);
    cudaGetSymbolAddress((void**)&v,   g_v);
    cudaGetSymbolAddress((void**)&a,   g_a);

    cudaFuncSetAttribute(gemm_h<0>, cudaFuncAttributeMaxDynamicSharedMemorySize, SMEM_TOTAL);
    cudaFuncSetAttribute(gemm_h<1>, cudaFuncAttributeMaxDynamicSharedMemorySize, SMEM_TOTAL);
    cudaFuncSetAttribute(gemm_h<2>, cudaFuncAttributeMaxDynamicSharedMemorySize, SMEM_TOTAL);
    cudaFuncSetAttribute(gemm_h<3>, cudaFuncAttributeMaxDynamicSharedMemorySize, SMEM_TOTAL);

    xpose_h<<<dim3(128, 16, 4), dim3(32, 8)>>>(x, xT);
    conv_pad_w<<<(1024*512 + 255)/256, 256>>>(Wq, bq, Wqh, bqp, 1024, 1000, 512);
    conv_pad_w<<<(1024*512 + 255)/256, 256>>>(Wk, bk, Wkh, bkp, 1024, 1000, 512);
    conv_pad_w<<<(512*512  + 255)/256, 256>>>(Wv, bv, Wvh, bvp,  512,  512, 512);

    const size_t sXT = (size_t)4096 * 512;
    const size_t sQT = (size_t)4096 * 1024;
    const size_t sV  = (size_t)512 * 4096;
    const size_t sAL = (size_t)4096 * 4096;
    const size_t sO  = (size_t)512 * 4096;

    // qT[n,o] = xT·Wq (M=4096,N=1024,K=512) + col bias
    gemm_h<1><<<dim3(4, 32, 4), 256, SMEM_TOTAL>>>(xT, sXT, Wqh, 0, q, sQT, bqp, 1024, 512);
    // kT[m,o] = xT·Wk
    gemm_h<1><<<dim3(4, 32, 4), 256, SMEM_TOTAL>>>(xT, sXT, Wkh, 0, k, sQT, bkp, 1024, 512);
    // v[c,n] = Wv·xT (M=512,N=4096,K=512) + row bias
    gemm_h<2><<<dim3(16, 4, 4), 256, SMEM_TOTAL>>>(Wvh, 0, xT, sXT, v, sV, bvp, 4096, 512);
    // aT[m,n] = sigmoid(kT·qT) (M=N=4096,K=1024)
    gemm_h<3><<<dim3(16, 32, 4), 256, SMEM_TOTAL>>>(k, sQT, q, sQT, a, sAL, nullptr, 4096, 1024);
    // out[c,m] = v·aT (M=512,N=4096,K=4096) fp32
    gemm_h<0><<<dim3(16, 4, 4), 256, SMEM_TOTAL>>>(v, sV, a, sAL, out, sO, nullptr, 4096, 4096);
}

// round 7
// speedup vs baseline: 1.0612x; 1.0612x over previous
#include <cuda_runtime.h>
#include <cuda_fp16.h>
#include <cstdint>
#include <cstddef>

// ---------------------------------------------------------------------------
// Sigmoid attention via fp16 mma.sync.m16n8k16 GEMMs (legacy HMMA path;
// tcgen05 unavailable: harness compiles through virtual arch compute_100).
// R7 = R4 mainloop (128x128 CTA, 4 warps of 64x64, 3-stage cp.async, 2 CTA/SM)
//  + merged Q/K GEMM against stacked [Wq;Wk] weights (halves xT traffic)
//  + batch-pair interleaved alpha/out launches so G5 reads alpha from L2.
//   qkT[n,0:1024]=q, [1024:2048]=k   (one GEMM, col bias)
//   v[c,n]   = Wv·xT + bv
//   aT[m,n]  = sigmoid(kT[m,:]·qT[n,:])      (A,B = strided halves of qkT)
//   out[c,m] = v[c,n]·aT[m,n]
// All GEMMs: D[m,n] = sum_k A[m,k]*B[n,k], A/B K-contiguous fp16, fp32 accum.
// ---------------------------------------------------------------------------

#define BM 128
#define BN 128
#define BKH 64                    // K halves per chunk (128 B per row)
#define STAGE 32768               // A tile 16KB + B tile 16KB
#define NSTAGE 3
#define SMEM_TOTAL (NSTAGE * STAGE)

// ------------------------------- scratch ------------------------------------
#define AL16 __align__(16)
static __device__ AL16 __half g_xT [(size_t)4*4096*512];    // xT[b][n][c]
static __device__ AL16 __half g_Wqk[2048*512];              // [Wq(1024 pad); Wk(1024 pad)]
static __device__ AL16 __half g_Wv [512*512];
static __device__ float g_bqk[2048], g_bv[512];
static __device__ AL16 __half g_qk [(size_t)4*4096*2048];   // qkT[b][n][0:1024]=q,[1024:2048]=k
static __device__ AL16 __half g_v  [(size_t)4*512*4096];    // v[b][c][n]
static __device__ AL16 __half g_a  [(size_t)4*4096*4096];   // aT[b][m][n]

// ------------------------------- helpers ------------------------------------
__device__ __forceinline__ void ldsm_x4(uint32_t& r0, uint32_t& r1, uint32_t& r2, uint32_t& r3,
                                        uint32_t addr) {
    asm volatile("ldmatrix.sync.aligned.m8n8.x4.shared.b16 {%0,%1,%2,%3}, [%4];"
                 : "=r"(r0), "=r"(r1), "=r"(r2), "=r"(r3) : "r"(addr));
}

__device__ __forceinline__ void mma_fp16(float* d, const uint32_t* a, const uint32_t* b) {
    asm volatile(
        "mma.sync.aligned.m16n8k16.row.col.f32.f16.f16.f32 "
        "{%0,%1,%2,%3}, {%4,%5,%6,%7}, {%8,%9}, {%0,%1,%2,%3};\n"
        : "+f"(d[0]), "+f"(d[1]), "+f"(d[2]), "+f"(d[3])
        : "r"(a[0]), "r"(a[1]), "r"(a[2]), "r"(a[3]), "r"(b[0]), "r"(b[1]));
}

// ---------------------------- prep kernels ----------------------------------
// x[b][c][n] fp32 -> xT[b][n][c] fp16
__global__ void xpose_h(const float* __restrict__ x, __half* __restrict__ xT) {
    __shared__ float t[32][33];
    const int b = blockIdx.z;
    const float* xb = x + (size_t)b * 512 * 4096;
    const int n0 = blockIdx.x * 32, c0 = blockIdx.y * 32;
    const int tx = threadIdx.x, ty0 = threadIdx.y;
#pragma unroll
    for (int i = 0; i < 4; i++) {
        int ty = ty0 + i * 8;
        t[ty][tx] = xb[(size_t)(c0 + ty) * 4096 + n0 + tx];
    }
    __syncthreads();
    const size_t ob = (size_t)b * 4096 * 512;
#pragma unroll
    for (int i = 0; i < 4; i++) {
        int ty = ty0 + i * 8;
        xT[ob + (size_t)(n0 + ty) * 512 + c0 + tx] = __float2half_rn(t[tx][ty]);
    }
}

// W[Mvalid][K] fp32 -> fp16 [Mout][K] zero-padded; bias padded
__global__ void conv_pad_w(const float* __restrict__ W, const float* __restrict__ b,
                           __half* __restrict__ Wh, float* __restrict__ bp,
                           int Mout, int Mvalid, int Kd) {
    int idx = blockIdx.x * blockDim.x + threadIdx.x;
    if (idx < Mout * Kd) {
        int m = idx / Kd;
        Wh[idx] = __float2half_rn((m < Mvalid) ? W[idx] : 0.0f);
    }
    if (idx < Mout) bp[idx] = (idx < Mvalid) ? b[idx] : 0.0f;
}

// ------------------------------- GEMM ---------------------------------------
// EPI: 0 = fp32 store ; 1 = +bias[col] -> fp16 ; 2 = +bias[row] -> fp16 ; 3 = sigmoid -> fp16
template <int EPI>
__global__ __launch_bounds__(128, 2)
void gemm_h(const __half* __restrict__ Ag, int lda, size_t sA,
            const __half* __restrict__ Bg, int ldb, size_t sB,
            void* Dg, int ldd, size_t sD,
            const float* __restrict__ bias,
            int K) {
    extern __shared__ __align__(1024) char smem[];
    const uint32_t sb = (uint32_t)__cvta_generic_to_shared(smem);

    const __half* A = Ag + (size_t)blockIdx.z * sA;
    const __half* B = Bg + (size_t)blockIdx.z * sB;
    const int m0 = blockIdx.y * BM;
    const int n0 = blockIdx.x * BN;
    const int tid  = threadIdx.x;
    const int lane = tid & 31;
    const int w    = tid >> 5;
    const int wm   = (w & 1) * 64;          // 2 warps over M
    const int wn   = (w >> 1) * 64;         // 2 warps over N
    const int g    = lane >> 2;
    const int tg   = lane & 3;

    const int T = K / BKH;

    auto load_stage = [&](int t, int s) {
        const uint32_t st = sb + (uint32_t)(s * STAGE);
        const int kc = t * BKH;
#pragma unroll
        for (int i = 0; i < 16; i++) {
            int idx = tid + i * 128;            // 0..2047
            int isB = idx >> 10;                // first 1024 A, then B
            int r   = (idx & 1023) >> 3;        // row 0..127
            int c   = idx & 7;                  // 16B chunk
            uint32_t dst = st + (uint32_t)(isB * 16384 + r * 128 + ((c ^ (r & 7)) << 4));
            const __half* gp = (isB ? B + (size_t)(n0 + r) * ldb
                                    : A + (size_t)(m0 + r) * lda) + kc + c * 8;
            asm volatile("cp.async.cg.shared.global [%0], [%1], 16;" :: "r"(dst), "l"(gp) : "memory");
        }
        asm volatile("cp.async.commit_group;" ::: "memory");
    };

    float acc[4][8][4];
#pragma unroll
    for (int i = 0; i < 4; i++)
#pragma unroll
        for (int j = 0; j < 8; j++)
#pragma unroll
            for (int r = 0; r < 4; r++) acc[i][j][r] = 0.0f;

    load_stage(0, 0);
    load_stage(1, 1);

    // ldmatrix lane addressing
    const int rowA = wm + (lane & 15);                        // + im*16
    const int hiA  = lane >> 4;                               // k8 chunk +0/+1
    const int rowB = wn + ((lane >> 4) << 3) + (lane & 7);    // + jn*16
    const int hiB  = (lane >> 3) & 1;

    for (int t = 0; t < T; t++) {
        asm volatile("cp.async.wait_group 1;" ::: "memory");
        __syncthreads();
        if (t + 2 < T) load_stage(t + 2, (t + 2) % NSTAGE);

        const uint32_t st  = sb + (uint32_t)((t % NSTAGE) * STAGE);
        const uint32_t stB = st + 16384;
#pragma unroll
        for (int ks = 0; ks < 4; ks++) {
            uint32_t af[4][4], bf[8][2];
#pragma unroll
            for (int im = 0; im < 4; im++) {
                const int r = rowA + im * 16;
                const int c = (ks * 2 + hiA) ^ (r & 7);
                ldsm_x4(af[im][0], af[im][1], af[im][2], af[im][3],
                        st + (uint32_t)(r * 128 + (c << 4)));
            }
#pragma unroll
            for (int jn = 0; jn < 4; jn++) {
                const int r = rowB + jn * 16;
                const int c = (ks * 2 + hiB) ^ (r & 7);
                ldsm_x4(bf[2*jn][0], bf[2*jn][1], bf[2*jn+1][0], bf[2*jn+1][1],
                        stB + (uint32_t)(r * 128 + (c << 4)));
            }
#pragma unroll
            for (int im = 0; im < 4; im++)
#pragma unroll
                for (int in = 0; in < 8; in++)
                    mma_fp16(acc[im][in], af[im], bf[in]);
        }
    }

    // ------------------------------ epilogue ---------------------------------
#pragma unroll
    for (int im = 0; im < 4; im++) {
        const int r0 = m0 + wm + im * 16 + g;
#pragma unroll
        for (int in = 0; in < 8; in++) {
            const int c = n0 + wn + in * 8 + 2 * tg;
#pragma unroll
            for (int h = 0; h < 2; h++) {
                const int r = r0 + h * 8;
                float vx = acc[im][in][2 * h];
                float vy = acc[im][in][2 * h + 1];
                if (EPI == 1) { vx += bias[c]; vy += bias[c + 1]; }
                if (EPI == 2) { float bb = bias[r]; vx += bb; vy += bb; }
                if (EPI == 3) {
                    vx = __fdividef(1.0f, 1.0f + __expf(-vx));
                    vy = __fdividef(1.0f, 1.0f + __expf(-vy));
                }
                if (EPI == 0) {
                    float* D = (float*)Dg + (size_t)blockIdx.z * sD + (size_t)r * ldd + c;
                    *reinterpret_cast<float2*>(D) = make_float2(vx, vy);
                } else {
                    __half* D = (__half*)Dg + (size_t)blockIdx.z * sD + (size_t)r * ldd + c;
                    *reinterpret_cast<__half2*>(D) = __floats2half2_rn(vx, vy);
                }
            }
        }
    }
}

// ------------------------------- launch -------------------------------------
extern "C" void kernel_launch(void* const* d_in, const int* in_sizes, int n_in,
                              void* d_out, int out_size) {
    (void)in_sizes; (void)n_in; (void)out_size;
    const float* x  = (const float*)d_in[0];
    const float* Wq = (const float*)d_in[1];
    const float* bq = (const float*)d_in[2];
    const float* Wk = (const float*)d_in[3];
    const float* bk = (const float*)d_in[4];
    const float* Wv = (const float*)d_in[5];
    const float* bv = (const float*)d_in[6];
    float* out = (float*)d_out;

    __half *xT,*Wqk,*Wvh,*qk,*v,*a;
    float *bqkp,*bvp;
    cudaGetSymbolAddress((void**)&xT,   g_xT);
    cudaGetSymbolAddress((void**)&Wqk,  g_Wqk);
    cudaGetSymbolAddress((void**)&Wvh,  g_Wv);
    cudaGetSymbolAddress((void**)&bqkp, g_bqk);
    cudaGetSymbolAddress((void**)&bvp,  g_bv);
    cudaGetSymbolAddress((void**)&qk,   g_qk);
    cudaGetSymbolAddress((void**)&v,    g_v);
    cudaGetSymbolAddress((void**)&a,    g_a);

    cudaFuncSetAttribute(gemm_h<0>, cudaFuncAttributeMaxDynamicSharedMemorySize, SMEM_TOTAL);
    cudaFuncSetAttribute(gemm_h<1>, cudaFuncAttributeMaxDynamicSharedMemorySize, SMEM_TOTAL);
    cudaFuncSetAttribute(gemm_h<2>, cudaFuncAttributeMaxDynamicSharedMemorySize, SMEM_TOTAL);
    cudaFuncSetAttribute(gemm_h<3>, cudaFuncAttributeMaxDynamicSharedMemorySize, SMEM_TOTAL);

    xpose_h<<<dim3(128, 16, 4), dim3(32, 8)>>>(x, xT);
    // stacked weights: rows 0..1023 = Wq (pad 1000->1024), rows 1024..2047 = Wk
    conv_pad_w<<<(1024*512 + 255)/256, 256>>>(Wq, bq, Wqk,            bqkp,        1024, 1000, 512);
    conv_pad_w<<<(1024*512 + 255)/256, 256>>>(Wk, bk, Wqk + 1024*512, bqkp + 1024, 1024, 1000, 512);
    conv_pad_w<<<(512*512  + 255)/256, 256>>>(Wv, bv, Wvh, bvp, 512, 512, 512);

    const size_t sXT = (size_t)4096 * 512;
    const size_t sQK = (size_t)4096 * 2048;
    const size_t sV  = (size_t)512 * 4096;
    const size_t sAL = (size_t)4096 * 4096;
    const size_t sO  = (size_t)512 * 4096;

    // v[c,n] = Wv·xT (M=512,N=4096,K=512) + row bias
    gemm_h<2><<<dim3(32, 4, 4), 128, SMEM_TOTAL>>>(Wvh, 512, 0, xT, 512, sXT, v, 4096, sV, bvp, 512);
    // qkT[n, 0:2048] = xT·[Wq;Wk] (M=4096,N=2048,K=512) + col bias
    gemm_h<1><<<dim3(16, 32, 4), 128, SMEM_TOTAL>>>(xT, 512, sXT, Wqk, 512, 0, qk, 2048, sQK, bqkp, 512);

    // batch pairs: alpha for 2 batches (67MB) stays L2-resident for the out GEMM
    for (int p = 0; p < 2; p++) {
        const __half* kT = qk + (size_t)p * 2 * sQK + 1024;   // kT[m][o] = qk[m][1024+o]
        const __half* qT = qk + (size_t)p * 2 * sQK;
        __half*       ap = a  + (size_t)p * 2 * sAL;
        const __half* vp = v  + (size_t)p * 2 * sV;
        float*        op = out + (size_t)p * 2 * sO;
        // aT[m,n] = sigmoid(kT·qT) (M=N=4096,K=1024), z=2 batches
        gemm_h<3><<<dim3(32, 32, 2), 128, SMEM_TOTAL>>>(kT, 2048, sQK, qT, 2048, sQK, ap, 4096, sAL, nullptr, 1024);
        // out[c,m] = v·aT (M=512,N=4096,K=4096) fp32, z=2 batches
        gemm_h<0><<<dim3(32, 4, 2), 128, SMEM_TOTAL>>>(vp, 4096, sV, ap, 4096, sAL, op, 4096, sO, nullptr, 4096);
    }
}

// round 8
// speedup vs baseline: 1.1719x; 1.1043x over previous
#include <cuda_runtime.h>
#include <cuda_fp16.h>
#include <cstdint>
#include <cstddef>

// ---------------------------------------------------------------------------
// Sigmoid attention, algebraically refactored (R8):
//   s[n,m] = (Wq x_n + bq)·(Wk x_m + bk)
//          = y_n·x_m + u·x_m + w·x_n + c0,
//     y[n,c'] = sum_c x[n,c]·M[c,c'],  M = Wq^T Wk  (512x512: O_CH contracts early)
//     u = Wk^T bq, w = Wq^T bk, c0 = bq·bk
// Pipeline (all GEMMs D[m,n] = sum_k A[m,k]*B[n,k], K-contiguous fp16, fp32 acc):
//   Mkq[c'][c] = (Wk^T Wq)      (K=1024 over padded o)
//   y[b][n][c'] = xT·Mkq        (K=512)
//   v[b][c][n'] = Wv·xT + bv    (K=512)
//   aT[b][m][n] = sigmoid(x_m·y_n + rb[m] + cb[n])   (K=512; was K=1024)
//   out[b][c][m] = v·aT         (K=4096)
// Mainloop = R4's proven shape: 128x128 CTA, 4 warps of 64x64, 3-stage
// cp.async, ldmatrix.x4, 2 CTA/SM. 249 -> 155 GF total.
// ---------------------------------------------------------------------------

#define BM 128
#define BN 128
#define STAGE 32768               // A tile 16KB + B tile 16KB
#define NSTAGE 3
#define SMEM_TOTAL (NSTAGE * STAGE)

// ------------------------------- scratch ------------------------------------
#define AL16 __align__(16)
static __device__ AL16 __half g_xT [(size_t)4*4096*512];    // xT[b][n][c]
static __device__ AL16 __half g_WqT[512*1024];              // Wq^T[c][o] (o pad 1000->1024)
static __device__ AL16 __half g_WkT[512*1024];              // Wk^T[c][o]
static __device__ AL16 __half g_Wv [512*512];               // Wv[c][c'] fp16
static __device__ AL16 __half g_M  [512*512];               // Mkq[c'][c] = (Wk^T Wq)
static __device__ AL16 __half g_y  [(size_t)4*4096*512];    // y[b][n][c']
static __device__ AL16 __half g_v  [(size_t)4*512*4096];    // v[b][c][n]
static __device__ AL16 __half g_a  [(size_t)4*4096*4096];   // aT[b][m][n]
static __device__ float g_bv[512];
static __device__ float g_u[512], g_w[512], g_c0[1];
static __device__ float g_rb[4*4096], g_cb[4*4096];         // row/col bias for alpha

// ------------------------------- helpers ------------------------------------
__device__ __forceinline__ void ldsm_x4(uint32_t& r0, uint32_t& r1, uint32_t& r2, uint32_t& r3,
                                        uint32_t addr) {
    asm volatile("ldmatrix.sync.aligned.m8n8.x4.shared.b16 {%0,%1,%2,%3}, [%4];"
                 : "=r"(r0), "=r"(r1), "=r"(r2), "=r"(r3) : "r"(addr));
}

__device__ __forceinline__ void mma_fp16(float* d, const uint32_t* a, const uint32_t* b) {
    asm volatile(
        "mma.sync.aligned.m16n8k16.row.col.f32.f16.f16.f32 "
        "{%0,%1,%2,%3}, {%4,%5,%6,%7}, {%8,%9}, {%0,%1,%2,%3};\n"
        : "+f"(d[0]), "+f"(d[1]), "+f"(d[2]), "+f"(d[3])
        : "r"(a[0]), "r"(a[1]), "r"(a[2]), "r"(a[3]), "r"(b[0]), "r"(b[1]));
}

// ---------------------------- prep kernels ----------------------------------
// x[b][c][n] fp32 -> xT[b][n][c] fp16
__global__ void xpose_h(const float* __restrict__ x, __half* __restrict__ xT) {
    __shared__ float t[32][33];
    const int b = blockIdx.z;
    const float* xb = x + (size_t)b * 512 * 4096;
    const int n0 = blockIdx.x * 32, c0 = blockIdx.y * 32;
    const int tx = threadIdx.x, ty0 = threadIdx.y;
#pragma unroll
    for (int i = 0; i < 4; i++) {
        int ty = ty0 + i * 8;
        t[ty][tx] = xb[(size_t)(c0 + ty) * 4096 + n0 + tx];
    }
    __syncthreads();
    const size_t ob = (size_t)b * 4096 * 512;
#pragma unroll
    for (int i = 0; i < 4; i++) {
        int ty = ty0 + i * 8;
        xT[ob + (size_t)(n0 + ty) * 512 + c0 + tx] = __float2half_rn(t[tx][ty]);
    }
}

// W fp32 [Rvalid][512] -> WT fp16 [512][Rpad], zero pad rows >= Rvalid
__global__ void xposew_h(const float* __restrict__ W, __half* __restrict__ WT,
                         int Rvalid, int Rpad) {
    __shared__ float t[32][33];
    const int r0 = blockIdx.x * 32, c0 = blockIdx.y * 32;
    const int tx = threadIdx.x, ty0 = threadIdx.y;
#pragma unroll
    for (int i = 0; i < 4; i++) {
        int ty = ty0 + i * 8;
        int r = r0 + ty;
        t[ty][tx] = (r < Rvalid) ? W[(size_t)r * 512 + c0 + tx] : 0.0f;
    }
    __syncthreads();
#pragma unroll
    for (int i = 0; i < 4; i++) {
        int ty = ty0 + i * 8;
        WT[(size_t)(c0 + ty) * Rpad + r0 + tx] = __float2half_rn(t[tx][ty]);
    }
}

// fp32 [512][512] -> fp16, plus bias copy
__global__ void conv_wv(const float* __restrict__ W, const float* __restrict__ b,
                        __half* __restrict__ Wh, float* __restrict__ bp) {
    int idx = blockIdx.x * blockDim.x + threadIdx.x;
    if (idx < 512 * 512) Wh[idx] = __float2half_rn(W[idx]);
    if (idx < 512) bp[idx] = b[idx];
}

// u = Wk^T bq, w = Wq^T bk, c0 = bq.bk   (original fp32 weights, 1000 rows)
__global__ void uw_kernel(const float* __restrict__ Wq, const float* __restrict__ bq,
                          const float* __restrict__ Wk, const float* __restrict__ bk,
                          float* __restrict__ u, float* __restrict__ w, float* __restrict__ c0) {
    int c = threadIdx.x;   // 512 threads
    float au = 0.f, aw = 0.f;
    for (int o = 0; o < 1000; o++) {
        au += Wk[(size_t)o * 512 + c] * bq[o];
        aw += Wq[(size_t)o * 512 + c] * bk[o];
    }
    u[c] = au; w[c] = aw;
    if (c == 0) {
        float s = 0.f;
        for (int o = 0; o < 1000; o++) s += bq[o] * bk[o];
        *c0 = s;
    }
}

// rb[row] = u.x_row ; cb[row] = w.x_row + c0   (row = b*4096+n over xT rows)
__global__ void rbcb_kernel(const __half* __restrict__ xT,
                            const float* __restrict__ u, const float* __restrict__ w,
                            const float* __restrict__ c0,
                            float* __restrict__ rb, float* __restrict__ cb) {
    int row = blockIdx.x * 8 + (threadIdx.x >> 5);
    int lane = threadIdx.x & 31;
    const __half* xr = xT + (size_t)row * 512;
    float au = 0.f, aw = 0.f;
#pragma unroll
    for (int j = 0; j < 16; j++) {
        int c = j * 32 + lane;
        float xv = __half2float(xr[c]);
        au += u[c] * xv;
        aw += w[c] * xv;
    }
#pragma unroll
    for (int off = 16; off > 0; off >>= 1) {
        au += __shfl_xor_sync(0xFFFFFFFF, au, off);
        aw += __shfl_xor_sync(0xFFFFFFFF, aw, off);
    }
    if (lane == 0) { rb[row] = au; cb[row] = aw + *c0; }
}

// ------------------------------- GEMM ---------------------------------------
// EPI: 0 = fp32 store, no bias       (out GEMM)
//      1 = fp16 store, no bias       (M GEMM, y GEMM)
//      2 = fp16 store, +bias1[row]   (v GEMM)
//      3 = fp16 store, sigmoid(acc + bias1[row] + bias2[col])   (alpha GEMM)
template <int EPI>
__global__ __launch_bounds__(128, 2)
void gemm_h(const __half* __restrict__ Ag, int lda, size_t sA,
            const __half* __restrict__ Bg, int ldb, size_t sB,
            void* Dg, int ldd, size_t sD,
            const float* __restrict__ bias1, int s1,
            const float* __restrict__ bias2, int s2,
            int K) {
    extern __shared__ __align__(1024) char smem[];
    const uint32_t sb = (uint32_t)__cvta_generic_to_shared(smem);

    const __half* A = Ag + (size_t)blockIdx.z * sA;
    const __half* B = Bg + (size_t)blockIdx.z * sB;
    const float* b1 = (EPI >= 2) ? bias1 + (size_t)blockIdx.z * s1 : nullptr;
    const float* b2 = (EPI == 3) ? bias2 + (size_t)blockIdx.z * s2 : nullptr;
    const int m0 = blockIdx.y * BM;
    const int n0 = blockIdx.x * BN;
    const int tid  = threadIdx.x;
    const int lane = tid & 31;
    const int w    = tid >> 5;
    const int wm   = (w & 1) * 64;          // 2 warps over M
    const int wn   = (w >> 1) * 64;         // 2 warps over N
    const int g    = lane >> 2;
    const int tg   = lane & 3;

    const int T = K / 64;

    auto load_stage = [&](int t, int s) {
        const uint32_t st = sb + (uint32_t)(s * STAGE);
        const int kc = t * 64;
#pragma unroll
        for (int i = 0; i < 16; i++) {
            int idx = tid + i * 128;            // 0..2047
            int isB = idx >> 10;                // first 1024 A, then B
            int r   = (idx & 1023) >> 3;        // row 0..127
            int c   = idx & 7;                  // 16B chunk
            uint32_t dst = st + (uint32_t)(isB * 16384 + r * 128 + ((c ^ (r & 7)) << 4));
            const __half* gp = (isB ? B + (size_t)(n0 + r) * ldb
                                    : A + (size_t)(m0 + r) * lda) + kc + c * 8;
            asm volatile("cp.async.cg.shared.global [%0], [%1], 16;" :: "r"(dst), "l"(gp) : "memory");
        }
        asm volatile("cp.async.commit_group;" ::: "memory");
    };

    float acc[4][8][4];
#pragma unroll
    for (int i = 0; i < 4; i++)
#pragma unroll
        for (int j = 0; j < 8; j++)
#pragma unroll
            for (int r = 0; r < 4; r++) acc[i][j][r] = 0.0f;

    load_stage(0, 0);
    load_stage(1, 1);

    // ldmatrix lane addressing
    const int rowA = wm + (lane & 15);                        // + im*16
    const int hiA  = lane >> 4;                               // k8 chunk +0/+1
    const int rowB = wn + ((lane >> 4) << 3) + (lane & 7);    // + jn*16
    const int hiB  = (lane >> 3) & 1;

    for (int t = 0; t < T; t++) {
        asm volatile("cp.async.wait_group 1;" ::: "memory");
        __syncthreads();
        if (t + 2 < T) load_stage(t + 2, (t + 2) % NSTAGE);

        const uint32_t st  = sb + (uint32_t)((t % NSTAGE) * STAGE);
        const uint32_t stB = st + 16384;
#pragma unroll
        for (int ks = 0; ks < 4; ks++) {
            uint32_t af[4][4], bf[8][2];
#pragma unroll
            for (int im = 0; im < 4; im++) {
                const int r = rowA + im * 16;
                const int c = (ks * 2 + hiA) ^ (r & 7);
                ldsm_x4(af[im][0], af[im][1], af[im][2], af[im][3],
                        st + (uint32_t)(r * 128 + (c << 4)));
            }
#pragma unroll
            for (int jn = 0; jn < 4; jn++) {
                const int r = rowB + jn * 16;
                const int c = (ks * 2 + hiB) ^ (r & 7);
                ldsm_x4(bf[2*jn][0], bf[2*jn][1], bf[2*jn+1][0], bf[2*jn+1][1],
                        stB + (uint32_t)(r * 128 + (c << 4)));
            }
#pragma unroll
            for (int im = 0; im < 4; im++)
#pragma unroll
                for (int in = 0; in < 8; in++)
                    mma_fp16(acc[im][in], af[im], bf[in]);
        }
    }

    // ------------------------------ epilogue ---------------------------------
#pragma unroll
    for (int im = 0; im < 4; im++) {
        const int r0 = m0 + wm + im * 16 + g;
#pragma unroll
        for (int in = 0; in < 8; in++) {
            const int c = n0 + wn + in * 8 + 2 * tg;
#pragma unroll
            for (int h = 0; h < 2; h++) {
                const int r = r0 + h * 8;
                float vx = acc[im][in][2 * h];
                float vy = acc[im][in][2 * h + 1];
                if (EPI == 2) { float bb = b1[r]; vx += bb; vy += bb; }
                if (EPI == 3) {
                    float bb = b1[r];
                    vx += bb + b2[c];
                    vy += bb + b2[c + 1];
                    vx = __fdividef(1.0f, 1.0f + __expf(-vx));
                    vy = __fdividef(1.0f, 1.0f + __expf(-vy));
                }
                if (EPI == 0) {
                    float* D = (float*)Dg + (size_t)blockIdx.z * sD + (size_t)r * ldd + c;
                    *reinterpret_cast<float2*>(D) = make_float2(vx, vy);
                } else {
                    __half* D = (__half*)Dg + (size_t)blockIdx.z * sD + (size_t)r * ldd + c;
                    *reinterpret_cast<__half2*>(D) = __floats2half2_rn(vx, vy);
                }
            }
        }
    }
}

// ------------------------------- launch -------------------------------------
extern "C" void kernel_launch(void* const* d_in, const int* in_sizes, int n_in,
                              void* d_out, int out_size) {
    (void)in_sizes; (void)n_in; (void)out_size;
    const float* x  = (const float*)d_in[0];
    const float* Wq = (const float*)d_in[1];
    const float* bq = (const float*)d_in[2];
    const float* Wk = (const float*)d_in[3];
    const float* bk = (const float*)d_in[4];
    const float* Wv = (const float*)d_in[5];
    const float* bv = (const float*)d_in[6];
    float* out = (float*)d_out;

    __half *xT,*WqT,*WkT,*Wvh,*M,*y,*v,*a;
    float *bvp,*u,*w,*c0,*rb,*cb;
    cudaGetSymbolAddress((void**)&xT,  g_xT);
    cudaGetSymbolAddress((void**)&WqT, g_WqT);
    cudaGetSymbolAddress((void**)&WkT, g_WkT);
    cudaGetSymbolAddress((void**)&Wvh, g_Wv);
    cudaGetSymbolAddress((void**)&M,   g_M);
    cudaGetSymbolAddress((void**)&y,   g_y);
    cudaGetSymbolAddress((void**)&v,   g_v);
    cudaGetSymbolAddress((void**)&a,   g_a);
    cudaGetSymbolAddress((void**)&bvp, g_bv);
    cudaGetSymbolAddress((void**)&u,   g_u);
    cudaGetSymbolAddress((void**)&w,   g_w);
    cudaGetSymbolAddress((void**)&c0,  g_c0);
    cudaGetSymbolAddress((void**)&rb,  g_rb);
    cudaGetSymbolAddress((void**)&cb,  g_cb);

    cudaFuncSetAttribute(gemm_h<0>, cudaFuncAttributeMaxDynamicSharedMemorySize, SMEM_TOTAL);
    cudaFuncSetAttribute(gemm_h<1>, cudaFuncAttributeMaxDynamicSharedMemorySize, SMEM_TOTAL);
    cudaFuncSetAttribute(gemm_h<2>, cudaFuncAttributeMaxDynamicSharedMemorySize, SMEM_TOTAL);
    cudaFuncSetAttribute(gemm_h<3>, cudaFuncAttributeMaxDynamicSharedMemorySize, SMEM_TOTAL);

    // ---- prep ----
    xpose_h<<<dim3(128, 16, 4), dim3(32, 8)>>>(x, xT);
    xposew_h<<<dim3(32, 16), dim3(32, 8)>>>(Wq, WqT, 1000, 1024);
    xposew_h<<<dim3(32, 16), dim3(32, 8)>>>(Wk, WkT, 1000, 1024);
    conv_wv<<<(512*512 + 255)/256, 256>>>(Wv, bv, Wvh, bvp);
    uw_kernel<<<1, 512>>>(Wq, bq, Wk, bk, u, w, c0);
    rbcb_kernel<<<2048, 256>>>(xT, u, w, c0, rb, cb);

    const size_t sXT = (size_t)4096 * 512;
    const size_t sY  = (size_t)4096 * 512;
    const size_t sV  = (size_t)512 * 4096;
    const size_t sAL = (size_t)4096 * 4096;
    const size_t sO  = (size_t)512 * 4096;

    // Mkq[c'][c] = Wk^T·Wq  (M=512,N=512,K=1024)
    gemm_h<1><<<dim3(4, 4, 1), 128, SMEM_TOTAL>>>(WkT, 1024, 0, WqT, 1024, 0,
                                                  M, 512, 0, nullptr, 0, nullptr, 0, 1024);
    // v[c][n'] = Wv·xT + bv  (M=512,N=4096,K=512)
    gemm_h<2><<<dim3(32, 4, 4), 128, SMEM_TOTAL>>>(Wvh, 512, 0, xT, 512, sXT,
                                                   v, 4096, sV, bvp, 0, nullptr, 0, 512);
    // y[n][c'] = xT·Mkq  (M=4096,N=512,K=512)
    gemm_h<1><<<dim3(4, 32, 4), 128, SMEM_TOTAL>>>(xT, 512, sXT, M, 512, 0,
                                                   y, 512, sY, nullptr, 0, nullptr, 0, 512);
    // aT[m][n] = sigmoid(x_m·y_n + rb[m] + cb[n])  (M=N=4096,K=512)
    gemm_h<3><<<dim3(32, 32, 4), 128, SMEM_TOTAL>>>(xT, 512, sXT, y, 512, sY,
                                                    a, 4096, sAL, rb, 4096, cb, 4096, 512);
    // out[c][m] = v·aT  (M=512,N=4096,K=4096) fp32
    gemm_h<0><<<dim3(32, 4, 4), 128, SMEM_TOTAL>>>(v, 4096, sV, a, 4096, sAL,
                                                   out, 4096, sO, nullptr, 0, nullptr, 0, 4096);
}

// round 9
// speedup vs baseline: 1.1871x; 1.0130x over previous
#include <cuda_runtime.h>
#include <cuda_fp16.h>
#include <cstdint>
#include <cstddef>

// ---------------------------------------------------------------------------
// Sigmoid attention, algebraically refactored (R8) + R9 stall fixes:
//   s[n,m] = y_n·x_m + u·x_m + w·x_n + c0,  y = x·(Wq^T Wk)  (O_CH contracts early)
// Pipeline (D[m,n] = sum_k A[m,k]*B[n,k], K-contiguous fp16, fp32 acc):
//   Mkq = Wk^T·Wq (512x512) ; y = xT·Mkq ; v = Wv·xT + bv
//   aT[m,n] = sigmoid(x_m·y_n + rb[m] + cb[n])   (K=512)
//   out = v·aT  (K=4096)
// R9: ks-loop fragment double-buffering (hide LDSM latency under MMA issue),
//     tanh.approx sigmoid epilogue. Mainloop otherwise R4-proven:
//     128x128 CTA, 4 warps of 64x64, 3-stage cp.async, 2 CTA/SM.
// ---------------------------------------------------------------------------

#define BM 128
#define BN 128
#define STAGE 32768               // A tile 16KB + B tile 16KB
#define NSTAGE 3
#define SMEM_TOTAL (NSTAGE * STAGE)

// ------------------------------- scratch ------------------------------------
#define AL16 __align__(16)
static __device__ AL16 __half g_xT [(size_t)4*4096*512];    // xT[b][n][c]
static __device__ AL16 __half g_WqT[512*1024];              // Wq^T[c][o] (o pad 1000->1024)
static __device__ AL16 __half g_WkT[512*1024];              // Wk^T[c][o]
static __device__ AL16 __half g_Wv [512*512];               // Wv[c][c'] fp16
static __device__ AL16 __half g_M  [512*512];               // Mkq[c'][c] = (Wk^T Wq)
static __device__ AL16 __half g_y  [(size_t)4*4096*512];    // y[b][n][c']
static __device__ AL16 __half g_v  [(size_t)4*512*4096];    // v[b][c][n]
static __device__ AL16 __half g_a  [(size_t)4*4096*4096];   // aT[b][m][n]
static __device__ float g_bv[512];
static __device__ float g_u[512], g_w[512], g_c0[1];
static __device__ float g_rb[4*4096], g_cb[4*4096];         // row/col bias for alpha

// ------------------------------- helpers ------------------------------------
__device__ __forceinline__ void ldsm_x4(uint32_t& r0, uint32_t& r1, uint32_t& r2, uint32_t& r3,
                                        uint32_t addr) {
    asm volatile("ldmatrix.sync.aligned.m8n8.x4.shared.b16 {%0,%1,%2,%3}, [%4];"
                 : "=r"(r0), "=r"(r1), "=r"(r2), "=r"(r3) : "r"(addr));
}

__device__ __forceinline__ void mma_fp16(float* d, const uint32_t* a, const uint32_t* b) {
    asm volatile(
        "mma.sync.aligned.m16n8k16.row.col.f32.f16.f16.f32 "
        "{%0,%1,%2,%3}, {%4,%5,%6,%7}, {%8,%9}, {%0,%1,%2,%3};\n"
        : "+f"(d[0]), "+f"(d[1]), "+f"(d[2]), "+f"(d[3])
        : "r"(a[0]), "r"(a[1]), "r"(a[2]), "r"(a[3]), "r"(b[0]), "r"(b[1]));
}

__device__ __forceinline__ float sigmoid_fast(float x) {
    float t;
    asm("tanh.approx.f32 %0, %1;" : "=f"(t) : "f"(0.5f * x));
    return 0.5f + 0.5f * t;
}

// ---------------------------- prep kernels ----------------------------------
// x[b][c][n] fp32 -> xT[b][n][c] fp16
__global__ void xpose_h(const float* __restrict__ x, __half* __restrict__ xT) {
    __shared__ float t[32][33];
    const int b = blockIdx.z;
    const float* xb = x + (size_t)b * 512 * 4096;
    const int n0 = blockIdx.x * 32, c0 = blockIdx.y * 32;
    const int tx = threadIdx.x, ty0 = threadIdx.y;
#pragma unroll
    for (int i = 0; i < 4; i++) {
        int ty = ty0 + i * 8;
        t[ty][tx] = xb[(size_t)(c0 + ty) * 4096 + n0 + tx];
    }
    __syncthreads();
    const size_t ob = (size_t)b * 4096 * 512;
#pragma unroll
    for (int i = 0; i < 4; i++) {
        int ty = ty0 + i * 8;
        xT[ob + (size_t)(n0 + ty) * 512 + c0 + tx] = __float2half_rn(t[tx][ty]);
    }
}

// W fp32 [Rvalid][512] -> WT fp16 [512][Rpad], zero pad rows >= Rvalid
__global__ void xposew_h(const float* __restrict__ W, __half* __restrict__ WT,
                         int Rvalid, int Rpad) {
    __shared__ float t[32][33];
    const int r0 = blockIdx.x * 32, c0 = blockIdx.y * 32;
    const int tx = threadIdx.x, ty0 = threadIdx.y;
#pragma unroll
    for (int i = 0; i < 4; i++) {
        int ty = ty0 + i * 8;
        int r = r0 + ty;
        t[ty][tx] = (r < Rvalid) ? W[(size_t)r * 512 + c0 + tx] : 0.0f;
    }
    __syncthreads();
#pragma unroll
    for (int i = 0; i < 4; i++) {
        int ty = ty0 + i * 8;
        WT[(size_t)(c0 + ty) * Rpad + r0 + tx] = __float2half_rn(t[tx][ty]);
    }
}

// fp32 [512][512] -> fp16, plus bias copy
__global__ void conv_wv(const float* __restrict__ W, const float* __restrict__ b,
                        __half* __restrict__ Wh, float* __restrict__ bp) {
    int idx = blockIdx.x * blockDim.x + threadIdx.x;
    if (idx < 512 * 512) Wh[idx] = __float2half_rn(W[idx]);
    if (idx < 512) bp[idx] = b[idx];
}

// u = Wk^T bq, w = Wq^T bk, c0 = bq.bk   (original fp32 weights, 1000 rows)
__global__ void uw_kernel(const float* __restrict__ Wq, const float* __restrict__ bq,
                          const float* __restrict__ Wk, const float* __restrict__ bk,
                          float* __restrict__ u, float* __restrict__ w, float* __restrict__ c0) {
    int c = threadIdx.x;   // 512 threads
    float au = 0.f, aw = 0.f;
    for (int o = 0; o < 1000; o++) {
        au += Wk[(size_t)o * 512 + c] * bq[o];
        aw += Wq[(size_t)o * 512 + c] * bk[o];
    }
    u[c] = au; w[c] = aw;
    if (c == 0) {
        float s = 0.f;
        for (int o = 0; o < 1000; o++) s += bq[o] * bk[o];
        *c0 = s;
    }
}

// rb[row] = u.x_row ; cb[row] = w.x_row + c0   (row = b*4096+n over xT rows)
__global__ void rbcb_kernel(const __half* __restrict__ xT,
                            const float* __restrict__ u, const float* __restrict__ w,
                            const float* __restrict__ c0,
                            float* __restrict__ rb, float* __restrict__ cb) {
    int row = blockIdx.x * 8 + (threadIdx.x >> 5);
    int lane = threadIdx.x & 31;
    const __half* xr = xT + (size_t)row * 512;
    float au = 0.f, aw = 0.f;
#pragma unroll
    for (int j = 0; j < 16; j++) {
        int c = j * 32 + lane;
        float xv = __half2float(xr[c]);
        au += u[c] * xv;
        aw += w[c] * xv;
    }
#pragma unroll
    for (int off = 16; off > 0; off >>= 1) {
        au += __shfl_xor_sync(0xFFFFFFFF, au, off);
        aw += __shfl_xor_sync(0xFFFFFFFF, aw, off);
    }
    if (lane == 0) { rb[row] = au; cb[row] = aw + *c0; }
}

// ------------------------------- GEMM ---------------------------------------
// EPI: 0 = fp32 store, no bias       (out GEMM)
//      1 = fp16 store, no bias       (M GEMM, y GEMM)
//      2 = fp16 store, +bias1[row]   (v GEMM)
//      3 = fp16 store, sigmoid(acc + bias1[row] + bias2[col])   (alpha GEMM)
template <int EPI>
__global__ __launch_bounds__(128, 2)
void gemm_h(const __half* __restrict__ Ag, int lda, size_t sA,
            const __half* __restrict__ Bg, int ldb, size_t sB,
            void* Dg, int ldd, size_t sD,
            const float* __restrict__ bias1, int s1,
            const float* __restrict__ bias2, int s2,
            int K) {
    extern __shared__ __align__(1024) char smem[];
    const uint32_t sb = (uint32_t)__cvta_generic_to_shared(smem);

    const __half* A = Ag + (size_t)blockIdx.z * sA;
    const __half* B = Bg + (size_t)blockIdx.z * sB;
    const float* b1 = (EPI >= 2) ? bias1 + (size_t)blockIdx.z * s1 : nullptr;
    const float* b2 = (EPI == 3) ? bias2 + (size_t)blockIdx.z * s2 : nullptr;
    const int m0 = blockIdx.y * BM;
    const int n0 = blockIdx.x * BN;
    const int tid  = threadIdx.x;
    const int lane = tid & 31;
    const int w    = tid >> 5;
    const int wm   = (w & 1) * 64;          // 2 warps over M
    const int wn   = (w >> 1) * 64;         // 2 warps over N
    const int g    = lane >> 2;
    const int tg   = lane & 3;

    const int T = K / 64;

    auto load_stage = [&](int t, int s) {
        const uint32_t st = sb + (uint32_t)(s * STAGE);
        const int kc = t * 64;
#pragma unroll
        for (int i = 0; i < 16; i++) {
            int idx = tid + i * 128;            // 0..2047
            int isB = idx >> 10;                // first 1024 A, then B
            int r   = (idx & 1023) >> 3;        // row 0..127
            int c   = idx & 7;                  // 16B chunk
            uint32_t dst = st + (uint32_t)(isB * 16384 + r * 128 + ((c ^ (r & 7)) << 4));
            const __half* gp = (isB ? B + (size_t)(n0 + r) * ldb
                                    : A + (size_t)(m0 + r) * lda) + kc + c * 8;
            asm volatile("cp.async.cg.shared.global [%0], [%1], 16;" :: "r"(dst), "l"(gp) : "memory");
        }
        asm volatile("cp.async.commit_group;" ::: "memory");
    };

    float acc[4][8][4];
#pragma unroll
    for (int i = 0; i < 4; i++)
#pragma unroll
        for (int j = 0; j < 8; j++)
#pragma unroll
            for (int r = 0; r < 4; r++) acc[i][j][r] = 0.0f;

    load_stage(0, 0);
    load_stage(1, 1);

    // ldmatrix lane addressing
    const int rowA = wm + (lane & 15);                        // + im*16
    const int hiA  = lane >> 4;                               // k8 chunk +0/+1
    const int rowB = wn + ((lane >> 4) << 3) + (lane & 7);    // + jn*16
    const int hiB  = (lane >> 3) & 1;

    for (int t = 0; t < T; t++) {
        asm volatile("cp.async.wait_group 1;" ::: "memory");
        __syncthreads();

        const uint32_t st  = sb + (uint32_t)((t % NSTAGE) * STAGE);
        const uint32_t stB = st + 16384;

        // double-buffered fragments: prefetch ks, compute ks while loading ks+1
        uint32_t af[2][4][4], bf[2][8][2];

        auto load_frags = [&](int ks, int buf) {
#pragma unroll
            for (int im = 0; im < 4; im++) {
                const int r = rowA + im * 16;
                const int c = (ks * 2 + hiA) ^ (r & 7);
                ldsm_x4(af[buf][im][0], af[buf][im][1], af[buf][im][2], af[buf][im][3],
                        st + (uint32_t)(r * 128 + (c << 4)));
            }
#pragma unroll
            for (int jn = 0; jn < 4; jn++) {
                const int r = rowB + jn * 16;
                const int c = (ks * 2 + hiB) ^ (r & 7);
                ldsm_x4(bf[buf][2*jn][0], bf[buf][2*jn][1], bf[buf][2*jn+1][0], bf[buf][2*jn+1][1],
                        stB + (uint32_t)(r * 128 + (c << 4)));
            }
        };

        load_frags(0, 0);
        if (t + 2 < T) load_stage(t + 2, (t + 2) % NSTAGE);

#pragma unroll
        for (int ks = 0; ks < 4; ks++) {
            const int cur = ks & 1;
            if (ks < 3) load_frags(ks + 1, cur ^ 1);
#pragma unroll
            for (int im = 0; im < 4; im++)
#pragma unroll
                for (int in = 0; in < 8; in++)
                    mma_fp16(acc[im][in], af[cur][im], bf[cur][in]);
        }
    }

    // ------------------------------ epilogue ---------------------------------
#pragma unroll
    for (int im = 0; im < 4; im++) {
        const int r0 = m0 + wm + im * 16 + g;
#pragma unroll
        for (int in = 0; in < 8; in++) {
            const int c = n0 + wn + in * 8 + 2 * tg;
#pragma unroll
            for (int h = 0; h < 2; h++) {
                const int r = r0 + h * 8;
                float vx = acc[im][in][2 * h];
                float vy = acc[im][in][2 * h + 1];
                if (EPI == 2) { float bb = b1[r]; vx += bb; vy += bb; }
                if (EPI == 3) {
                    float bb = b1[r];
                    vx = sigmoid_fast(vx + bb + b2[c]);
                    vy = sigmoid_fast(vy + bb + b2[c + 1]);
                }
                if (EPI == 0) {
                    float* D = (float*)Dg + (size_t)blockIdx.z * sD + (size_t)r * ldd + c;
                    *reinterpret_cast<float2*>(D) = make_float2(vx, vy);
                } else {
                    __half* D = (__half*)Dg + (size_t)blockIdx.z * sD + (size_t)r * ldd + c;
                    *reinterpret_cast<__half2*>(D) = __floats2half2_rn(vx, vy);
                }
            }
        }
    }
}

// ------------------------------- launch -------------------------------------
extern "C" void kernel_launch(void* const* d_in, const int* in_sizes, int n_in,
                              void* d_out, int out_size) {
    (void)in_sizes; (void)n_in; (void)out_size;
    const float* x  = (const float*)d_in[0];
    const float* Wq = (const float*)d_in[1];
    const float* bq = (const float*)d_in[2];
    const float* Wk = (const float*)d_in[3];
    const float* bk = (const float*)d_in[4];
    const float* Wv = (const float*)d_in[5];
    const float* bv = (const float*)d_in[6];
    float* out = (float*)d_out;

    __half *xT,*WqT,*WkT,*Wvh,*M,*y,*v,*a;
    float *bvp,*u,*w,*c0,*rb,*cb;
    cudaGetSymbolAddress((void**)&xT,  g_xT);
    cudaGetSymbolAddress((void**)&WqT, g_WqT);
    cudaGetSymbolAddress((void**)&WkT, g_WkT);
    cudaGetSymbolAddress((void**)&Wvh, g_Wv);
    cudaGetSymbolAddress((void**)&M,   g_M);
    cudaGetSymbolAddress((void**)&y,   g_y);
    cudaGetSymbolAddress((void**)&v,   g_v);
    cudaGetSymbolAddress((void**)&a,   g_a);
    cudaGetSymbolAddress((void**)&bvp, g_bv);
    cudaGetSymbolAddress((void**)&u,   g_u);
    cudaGetSymbolAddress((void**)&w,   g_w);
    cudaGetSymbolAddress((void**)&c0,  g_c0);
    cudaGetSymbolAddress((void**)&rb,  g_rb);
    cudaGetSymbolAddress((void**)&cb,  g_cb);

    cudaFuncSetAttribute(gemm_h<0>, cudaFuncAttributeMaxDynamicSharedMemorySize, SMEM_TOTAL);
    cudaFuncSetAttribute(gemm_h<1>, cudaFuncAttributeMaxDynamicSharedMemorySize, SMEM_TOTAL);
    cudaFuncSetAttribute(gemm_h<2>, cudaFuncAttributeMaxDynamicSharedMemorySize, SMEM_TOTAL);
    cudaFuncSetAttribute(gemm_h<3>, cudaFuncAttributeMaxDynamicSharedMemorySize, SMEM_TOTAL);

    // ---- prep ----
    xpose_h<<<dim3(128, 16, 4), dim3(32, 8)>>>(x, xT);
    xposew_h<<<dim3(32, 16), dim3(32, 8)>>>(Wq, WqT, 1000, 1024);
    xposew_h<<<dim3(32, 16), dim3(32, 8)>>>(Wk, WkT, 1000, 1024);
    conv_wv<<<(512*512 + 255)/256, 256>>>(Wv, bv, Wvh, bvp);
    uw_kernel<<<1, 512>>>(Wq, bq, Wk, bk, u, w, c0);
    rbcb_kernel<<<2048, 256>>>(xT, u, w, c0, rb, cb);

    const size_t sXT = (size_t)4096 * 512;
    const size_t sY  = (size_t)4096 * 512;
    const size_t sV  = (size_t)512 * 4096;
    const size_t sAL = (size_t)4096 * 4096;
    const size_t sO  = (size_t)512 * 4096;

    // Mkq[c'][c] = Wk^T·Wq  (M=512,N=512,K=1024)
    gemm_h<1><<<dim3(4, 4, 1), 128, SMEM_TOTAL>>>(WkT, 1024, 0, WqT, 1024, 0,
                                                  M, 512, 0, nullptr, 0, nullptr, 0, 1024);
    // v[c][n'] = Wv·xT + bv  (M=512,N=4096,K=512)
    gemm_h<2><<<dim3(32, 4, 4), 128, SMEM_TOTAL>>>(Wvh, 512, 0, xT, 512, sXT,
                                                   v, 4096, sV, bvp, 0, nullptr, 0, 512);
    // y[n][c'] = xT·Mkq  (M=4096,N=512,K=512)
    gemm_h<1><<<dim3(4, 32, 4), 128, SMEM_TOTAL>>>(xT, 512, sXT, M, 512, 0,
                                                   y, 512, sY, nullptr, 0, nullptr, 0, 512);
    // aT[m][n] = sigmoid(x_m·y_n + rb[m] + cb[n])  (M=N=4096,K=512)
    gemm_h<3><<<dim3(32, 32, 4), 128, SMEM_TOTAL>>>(xT, 512, sXT, y, 512, sY,
                                                    a, 4096, sAL, rb, 4096, cb, 4096, 512);
    // out[c][m] = v·aT  (M=512,N=4096,K=4096) fp32
    gemm_h<0><<<dim3(32, 4, 4), 128, SMEM_TOTAL>>>(v, 4096, sV, a, 4096, sAL,
                                                   out, 4096, sO, nullptr, 0, nullptr, 0, 4096);
}

// round 11
// speedup vs baseline: 1.4960x; 1.2602x over previous
#include <cuda_runtime.h>
#include <cuda_fp16.h>
#include <cstdint>
#include <cstddef>

// ---------------------------------------------------------------------------
// Sigmoid attention, algebraically refactored (R8/R9) + R11 (= R10 with the
// prep_weights Wv-coverage bug fixed: z==2 branch now converts ALL 512x512
// elements; R10 converted only the first half, zeroing half of Wv).
//   s[n,m] = y_n·x_m + u·x_m + w·x_n + c0,  y = x·(Wq^T Wk)  (O_CH contracts early)
// Pipeline (D[m,n] = sum_k A[m,k]*B[n,k], K-contiguous fp16, fp32 acc):
//   Mkq = Wk^T·Wq (512x512) ; {y = xT·Mkq ; v = Wv·xT + bv} merged in ONE launch
//   aT[m,n] = sigmoid(x_m·y_n + rb[m] + cb[n])   (K=512)
//   out = v·aT  (K=4096)
// Hot GEMM mainloop unchanged from R9 (128x128 CTA, 4 warps of 64x64, 3-stage
// cp.async, ldmatrix.x4 double-buffered fragments, 2 CTA/SM).
// ---------------------------------------------------------------------------

#define BM 128
#define BN 128
#define STAGE 32768               // A tile 16KB + B tile 16KB
#define NSTAGE 3
#define SMEM_TOTAL (NSTAGE * STAGE)

// ------------------------------- scratch ------------------------------------
#define AL16 __align__(16)
static __device__ AL16 __half g_xT [(size_t)4*4096*512];    // xT[b][n][c]
static __device__ AL16 __half g_WqT[512*1024];              // Wq^T[c][o] (o pad 1000->1024)
static __device__ AL16 __half g_WkT[512*1024];              // Wk^T[c][o]
static __device__ AL16 __half g_Wv [512*512];               // Wv[c][c'] fp16
static __device__ AL16 __half g_M  [512*512];               // Mkq = Wk^T·Wq
static __device__ AL16 __half g_y  [(size_t)4*4096*512];    // y[b][n][c']
static __device__ AL16 __half g_v  [(size_t)4*512*4096];    // v[b][c][n]
static __device__ AL16 __half g_a  [(size_t)4*4096*4096];   // aT[b][m][n]
static __device__ float g_bv[512];
static __device__ float g_u[512], g_w[512], g_c0[1];
static __device__ float g_rb[4*4096], g_cb[4*4096];         // row/col bias for alpha

// ------------------------------- helpers ------------------------------------
__device__ __forceinline__ void ldsm_x4(uint32_t& r0, uint32_t& r1, uint32_t& r2, uint32_t& r3,
                                        uint32_t addr) {
    asm volatile("ldmatrix.sync.aligned.m8n8.x4.shared.b16 {%0,%1,%2,%3}, [%4];"
                 : "=r"(r0), "=r"(r1), "=r"(r2), "=r"(r3) : "r"(addr));
}

__device__ __forceinline__ void mma_fp16(float* d, const uint32_t* a, const uint32_t* b) {
    asm volatile(
        "mma.sync.aligned.m16n8k16.row.col.f32.f16.f16.f32 "
        "{%0,%1,%2,%3}, {%4,%5,%6,%7}, {%8,%9}, {%0,%1,%2,%3};\n"
        : "+f"(d[0]), "+f"(d[1]), "+f"(d[2]), "+f"(d[3])
        : "r"(a[0]), "r"(a[1]), "r"(a[2]), "r"(a[3]), "r"(b[0]), "r"(b[1]));
}

__device__ __forceinline__ float sigmoid_fast(float x) {
    float t;
    asm("tanh.approx.f32 %0, %1;" : "=f"(t) : "f"(0.5f * x));
    return 0.5f + 0.5f * t;
}

// ---------------------------- prep kernels ----------------------------------
// x[b][c][n] fp32 -> xT[b][n][c] fp16
__global__ void xpose_h(const float* __restrict__ x, __half* __restrict__ xT) {
    __shared__ float t[32][33];
    const int b = blockIdx.z;
    const float* xb = x + (size_t)b * 512 * 4096;
    const int n0 = blockIdx.x * 32, c0 = blockIdx.y * 32;
    const int tx = threadIdx.x, ty0 = threadIdx.y;
#pragma unroll
    for (int i = 0; i < 4; i++) {
        int ty = ty0 + i * 8;
        t[ty][tx] = xb[(size_t)(c0 + ty) * 4096 + n0 + tx];
    }
    __syncthreads();
    const size_t ob = (size_t)b * 4096 * 512;
#pragma unroll
    for (int i = 0; i < 4; i++) {
        int ty = ty0 + i * 8;
        xT[ob + (size_t)(n0 + ty) * 512 + c0 + tx] = __float2half_rn(t[tx][ty]);
    }
}

// merged weight prep: z=0 -> Wq^T, z=1 -> Wk^T, z=2 -> Wv fp16 + bv copy
__global__ void prep_weights(const float* __restrict__ Wq, const float* __restrict__ Wk,
                             const float* __restrict__ Wv, const float* __restrict__ bv,
                             __half* __restrict__ WqT, __half* __restrict__ WkT,
                             __half* __restrict__ Wvh, float* __restrict__ bvp) {
    const int z = blockIdx.z;
    if (z < 2) {
        __shared__ float t[32][33];
        const float* W = z ? Wk : Wq;
        __half* WT = z ? WkT : WqT;
        const int r0 = blockIdx.x * 32, c0 = blockIdx.y * 32;
        const int tx = threadIdx.x, ty0 = threadIdx.y;
#pragma unroll
        for (int i = 0; i < 4; i++) {
            int ty = ty0 + i * 8;
            int r = r0 + ty;
            t[ty][tx] = (r < 1000) ? W[(size_t)r * 512 + c0 + tx] : 0.0f;
        }
        __syncthreads();
#pragma unroll
        for (int i = 0; i < 4; i++) {
            int ty = ty0 + i * 8;
            WT[(size_t)(c0 + ty) * 1024 + r0 + tx] = __float2half_rn(t[tx][ty]);
        }
    } else {
        // 512 blocks x 256 threads x 2 elements = 262144 = full Wv coverage
        int idx = (blockIdx.y * 32 + blockIdx.x) * 256 + threadIdx.y * 32 + threadIdx.x;
        Wvh[idx]          = __float2half_rn(Wv[idx]);
        Wvh[idx + 131072] = __float2half_rn(Wv[idx + 131072]);
        if (idx < 512) bvp[idx] = bv[idx];
    }
}

// u = Wk^T bq, w = Wq^T bk, c0 = bq.bk   (parallel: warp per channel)
__global__ void uw_kernel(const float* __restrict__ Wq, const float* __restrict__ bq,
                          const float* __restrict__ Wk, const float* __restrict__ bk,
                          float* __restrict__ u, float* __restrict__ w, float* __restrict__ c0) {
    const int lane = threadIdx.x & 31;
    if (blockIdx.x == 64) {
        if ((threadIdx.x >> 5) == 0) {
            float s = 0.f;
            for (int o = lane; o < 1000; o += 32) s += bq[o] * bk[o];
#pragma unroll
            for (int off = 16; off > 0; off >>= 1) s += __shfl_xor_sync(0xFFFFFFFF, s, off);
            if (lane == 0) *c0 = s;
        }
        return;
    }
    const int c = blockIdx.x * 8 + (threadIdx.x >> 5);
    float au = 0.f, aw = 0.f;
    for (int o = lane; o < 1000; o += 32) {
        au += Wk[(size_t)o * 512 + c] * bq[o];
        aw += Wq[(size_t)o * 512 + c] * bk[o];
    }
#pragma unroll
    for (int off = 16; off > 0; off >>= 1) {
        au += __shfl_xor_sync(0xFFFFFFFF, au, off);
        aw += __shfl_xor_sync(0xFFFFFFFF, aw, off);
    }
    if (lane == 0) { u[c] = au; w[c] = aw; }
}

// rb[row] = u.x_row ; cb[row] = w.x_row + c0
__global__ void rbcb_kernel(const __half* __restrict__ xT,
                            const float* __restrict__ u, const float* __restrict__ w,
                            const float* __restrict__ c0,
                            float* __restrict__ rb, float* __restrict__ cb) {
    int row = blockIdx.x * 8 + (threadIdx.x >> 5);
    int lane = threadIdx.x & 31;
    const __half* xr = xT + (size_t)row * 512;
    float au = 0.f, aw = 0.f;
#pragma unroll
    for (int j = 0; j < 16; j++) {
        int c = j * 32 + lane;
        float xv = __half2float(xr[c]);
        au += u[c] * xv;
        aw += w[c] * xv;
    }
#pragma unroll
    for (int off = 16; off > 0; off >>= 1) {
        au += __shfl_xor_sync(0xFFFFFFFF, au, off);
        aw += __shfl_xor_sync(0xFFFFFFFF, aw, off);
    }
    if (lane == 0) { rb[row] = au; cb[row] = aw + *c0; }
}

// ------------------------- GEMM mainloop (macro body) ------------------------
#define GEMM_BODY(A_, lda_, B_, ldb_, K_)                                           \
    extern __shared__ __align__(1024) char smem[];                                  \
    const uint32_t sb = (uint32_t)__cvta_generic_to_shared(smem);                   \
    const int tid  = threadIdx.x;                                                   \
    const int lane = tid & 31;                                                      \
    const int w    = tid >> 5;                                                      \
    const int wm   = (w & 1) * 64;                                                  \
    const int wn   = (w >> 1) * 64;                                                 \
    const int g    = lane >> 2;                                                     \
    const int tg   = lane & 3;                                                      \
    const int T = (K_) / 64;                                                        \
    auto load_stage = [&](int t, int s) {                                           \
        const uint32_t st = sb + (uint32_t)(s * STAGE);                             \
        const int kc = t * 64;                                                      \
_Pragma("unroll")                                                                   \
        for (int i = 0; i < 16; i++) {                                              \
            int idx = tid + i * 128;                                                \
            int isB = idx >> 10;                                                    \
            int r   = (idx & 1023) >> 3;                                            \
            int c   = idx & 7;                                                      \
            uint32_t dst = st + (uint32_t)(isB * 16384 + r * 128 + ((c ^ (r & 7)) << 4)); \
            const __half* gp = (isB ? (B_) + (size_t)(n0 + r) * (ldb_)              \
                                    : (A_) + (size_t)(m0 + r) * (lda_)) + kc + c * 8; \
            asm volatile("cp.async.cg.shared.global [%0], [%1], 16;" :: "r"(dst), "l"(gp) : "memory"); \
        }                                                                           \
        asm volatile("cp.async.commit_group;" ::: "memory");                        \
    };                                                                              \
    float acc[4][8][4];                                                             \
_Pragma("unroll")                                                                   \
    for (int i = 0; i < 4; i++)                                                     \
_Pragma("unroll")                                                                   \
        for (int j = 0; j < 8; j++)                                                 \
_Pragma("unroll")                                                                   \
            for (int r = 0; r < 4; r++) acc[i][j][r] = 0.0f;                        \
    load_stage(0, 0);                                                               \
    load_stage(1, 1);                                                               \
    const int rowA = wm + (lane & 15);                                              \
    const int hiA  = lane >> 4;                                                     \
    const int rowB = wn + ((lane >> 4) << 3) + (lane & 7);                          \
    const int hiB  = (lane >> 3) & 1;                                               \
    for (int t = 0; t < T; t++) {                                                   \
        asm volatile("cp.async.wait_group 1;" ::: "memory");                        \
        __syncthreads();                                                            \
        const uint32_t st  = sb + (uint32_t)((t % NSTAGE) * STAGE);                 \
        const uint32_t stB = st + 16384;                                            \
        uint32_t af[2][4][4], bf[2][8][2];                                          \
        auto load_frags = [&](int ks, int buf) {                                    \
_Pragma("unroll")                                                                   \
            for (int im = 0; im < 4; im++) {                                        \
                const int r = rowA + im * 16;                                       \
                const int c = (ks * 2 + hiA) ^ (r & 7);                             \
                ldsm_x4(af[buf][im][0], af[buf][im][1], af[buf][im][2], af[buf][im][3], \
                        st + (uint32_t)(r * 128 + (c << 4)));                       \
            }                                                                       \
_Pragma("unroll")                                                                   \
            for (int jn = 0; jn < 4; jn++) {                                        \
                const int r = rowB + jn * 16;                                       \
                const int c = (ks * 2 + hiB) ^ (r & 7);                             \
                ldsm_x4(bf[buf][2*jn][0], bf[buf][2*jn][1], bf[buf][2*jn+1][0], bf[buf][2*jn+1][1], \
                        stB + (uint32_t)(r * 128 + (c << 4)));                      \
            }                                                                       \
        };                                                                          \
        load_frags(0, 0);                                                           \
        if (t + 2 < T) load_stage(t + 2, (t + 2) % NSTAGE);                         \
_Pragma("unroll")                                                                   \
        for (int ks = 0; ks < 4; ks++) {                                            \
            const int cur = ks & 1;                                                 \
            if (ks < 3) load_frags(ks + 1, cur ^ 1);                                \
_Pragma("unroll")                                                                   \
            for (int im = 0; im < 4; im++)                                          \
_Pragma("unroll")                                                                   \
                for (int in = 0; in < 8; in++)                                      \
                    mma_fp16(acc[im][in], af[cur][im], bf[cur][in]);                \
        }                                                                           \
    }

// ---------------------- hot GEMM (templated epilogue) ------------------------
// EPI: 0 = fp32 store (out) ; 1 = fp16 store (M) ; 3 = sigmoid+biases (alpha)
template <int EPI>
__global__ __launch_bounds__(128, 2)
void gemm_h(const __half* __restrict__ Ag, int lda, size_t sA,
            const __half* __restrict__ Bg, int ldb, size_t sB,
            void* Dg, int ldd, size_t sD,
            const float* __restrict__ bias1, int s1,
            const float* __restrict__ bias2, int s2,
            int K) {
    const __half* A = Ag + (size_t)blockIdx.z * sA;
    const __half* B = Bg + (size_t)blockIdx.z * sB;
    const float* b1 = (EPI == 3) ? bias1 + (size_t)blockIdx.z * s1 : nullptr;
    const float* b2 = (EPI == 3) ? bias2 + (size_t)blockIdx.z * s2 : nullptr;
    const int m0 = blockIdx.y * BM;
    const int n0 = blockIdx.x * BN;

    GEMM_BODY(A, lda, B, ldb, K)

#pragma unroll
    for (int im = 0; im < 4; im++) {
        const int r0 = m0 + wm + im * 16 + g;
#pragma unroll
        for (int in = 0; in < 8; in++) {
            const int c = n0 + wn + in * 8 + 2 * tg;
#pragma unroll
            for (int h = 0; h < 2; h++) {
                const int r = r0 + h * 8;
                float vx = acc[im][in][2 * h];
                float vy = acc[im][in][2 * h + 1];
                if (EPI == 3) {
                    float bb = b1[r];
                    vx = sigmoid_fast(vx + bb + b2[c]);
                    vy = sigmoid_fast(vy + bb + b2[c + 1]);
                }
                if (EPI == 0) {
                    float* D = (float*)Dg + (size_t)blockIdx.z * sD + (size_t)r * ldd + c;
                    *reinterpret_cast<float2*>(D) = make_float2(vx, vy);
                } else {
                    __half* D = (__half*)Dg + (size_t)blockIdx.z * sD + (size_t)r * ldd + c;
                    *reinterpret_cast<__half2*>(D) = __floats2half2_rn(vx, vy);
                }
            }
        }
    }
}

// ------------- merged v/y GEMM: one launch, runtime op select ----------------
// grid (128, 1, 8): z<4 -> v GEMM batch z (row-bias epi); z>=4 -> y GEMM batch z-4.
__global__ __launch_bounds__(128, 2)
void gemm_dual(const __half* __restrict__ Wvh, const __half* __restrict__ xT,
               const __half* __restrict__ Mkq,
               __half* __restrict__ v, __half* __restrict__ y,
               const float* __restrict__ bvp) {
    const size_t sXT = (size_t)4096 * 512;
    const int z = blockIdx.z;
    const int isV = (z < 4);
    const int b = isV ? z : z - 4;
    const int id = blockIdx.x;

    const __half* A;  const __half* B;  __half* D;
    int lda, ldb, ldd, m0, n0;
    const float* b1 = nullptr;
    if (isV) {         // v[c][n'] = Wv·xT + bv : M=512, N=4096, K=512; grid 4m x 32n
        A = Wvh; lda = 512;
        B = xT + (size_t)b * sXT; ldb = 512;
        D = v + (size_t)b * ((size_t)512 * 4096); ldd = 4096;
        m0 = (id >> 5) * BM;  n0 = (id & 31) * BN;
        b1 = bvp;
    } else {           // y[n][c'] = xT·Mkq : M=4096, N=512, K=512; grid 32m x 4n
        A = xT + (size_t)b * sXT; lda = 512;
        B = Mkq; ldb = 512;
        D = y + (size_t)b * sXT; ldd = 512;
        m0 = (id >> 2) * BM;  n0 = (id & 3) * BN;
    }

    GEMM_BODY(A, lda, B, ldb, 512)

#pragma unroll
    for (int im = 0; im < 4; im++) {
        const int r0 = m0 + wm + im * 16 + g;
#pragma unroll
        for (int in = 0; in < 8; in++) {
            const int c = n0 + wn + in * 8 + 2 * tg;
#pragma unroll
            for (int h = 0; h < 2; h++) {
                const int r = r0 + h * 8;
                float vx = acc[im][in][2 * h];
                float vy = acc[im][in][2 * h + 1];
                if (isV) { float bb = b1[r]; vx += bb; vy += bb; }
                __half* Dp = D + (size_t)r * ldd + c;
                *reinterpret_cast<__half2*>(Dp) = __floats2half2_rn(vx, vy);
            }
        }
    }
}

// ------------------------------- launch -------------------------------------
extern "C" void kernel_launch(void* const* d_in, const int* in_sizes, int n_in,
                              void* d_out, int out_size) {
    (void)in_sizes; (void)n_in; (void)out_size;
    const float* x  = (const float*)d_in[0];
    const float* Wq = (const float*)d_in[1];
    const float* bq = (const float*)d_in[2];
    const float* Wk = (const float*)d_in[3];
    const float* bk = (const float*)d_in[4];
    const float* Wv = (const float*)d_in[5];
    const float* bv = (const float*)d_in[6];
    float* out = (float*)d_out;

    __half *xT,*WqT,*WkT,*Wvh,*M,*y,*v,*a;
    float *bvp,*u,*w,*c0,*rb,*cb;
    cudaGetSymbolAddress((void**)&xT,  g_xT);
    cudaGetSymbolAddress((void**)&WqT, g_WqT);
    cudaGetSymbolAddress((void**)&WkT, g_WkT);
    cudaGetSymbolAddress((void**)&Wvh, g_Wv);
    cudaGetSymbolAddress((void**)&M,   g_M);
    cudaGetSymbolAddress((void**)&y,   g_y);
    cudaGetSymbolAddress((void**)&v,   g_v);
    cudaGetSymbolAddress((void**)&a,   g_a);
    cudaGetSymbolAddress((void**)&bvp, g_bv);
    cudaGetSymbolAddress((void**)&u,   g_u);
    cudaGetSymbolAddress((void**)&w,   g_w);
    cudaGetSymbolAddress((void**)&c0,  g_c0);
    cudaGetSymbolAddress((void**)&rb,  g_rb);
    cudaGetSymbolAddress((void**)&cb,  g_cb);

    cudaFuncSetAttribute(gemm_h<0>, cudaFuncAttributeMaxDynamicSharedMemorySize, SMEM_TOTAL);
    cudaFuncSetAttribute(gemm_h<1>, cudaFuncAttributeMaxDynamicSharedMemorySize, SMEM_TOTAL);
    cudaFuncSetAttribute(gemm_h<3>, cudaFuncAttributeMaxDynamicSharedMemorySize, SMEM_TOTAL);
    cudaFuncSetAttribute(gemm_dual, cudaFuncAttributeMaxDynamicSharedMemorySize, SMEM_TOTAL);

    // ---- prep ----
    prep_weights<<<dim3(32, 16, 3), dim3(32, 8)>>>(Wq, Wk, Wv, bv, WqT, WkT, Wvh, bvp);
    xpose_h<<<dim3(128, 16, 4), dim3(32, 8)>>>(x, xT);
    uw_kernel<<<65, 256>>>(Wq, bq, Wk, bk, u, w, c0);
    rbcb_kernel<<<2048, 256>>>(xT, u, w, c0, rb, cb);

    const size_t sXT = (size_t)4096 * 512;
    const size_t sV  = (size_t)512 * 4096;
    const size_t sAL = (size_t)4096 * 4096;
    const size_t sO  = (size_t)512 * 4096;

    // Mkq = Wk^T·Wq  (M=512,N=512,K=1024)
    gemm_h<1><<<dim3(4, 4, 1), 128, SMEM_TOTAL>>>(WkT, 1024, 0, WqT, 1024, 0,
                                                  M, 512, 0, nullptr, 0, nullptr, 0, 1024);
    // merged: v = Wv·xT + bv  AND  y = xT·Mkq   (one 1024-CTA launch)
    gemm_dual<<<dim3(128, 1, 8), 128, SMEM_TOTAL>>>(Wvh, xT, M, v, y, bvp);
    // aT[m][n] = sigmoid(x_m·y_n + rb[m] + cb[n])  (M=N=4096,K=512)
    gemm_h<3><<<dim3(32, 32, 4), 128, SMEM_TOTAL>>>(xT, 512, sXT, y, 512, sXT,
                                                    a, 4096, sAL, rb, 4096, cb, 4096, 512);
    // out[c][m] = v·aT  (M=512,N=4096,K=4096) fp32
    gemm_h<0><<<dim3(32, 4, 4), 128, SMEM_TOTAL>>>(v, 4096, sV, a, 4096, sAL,
                                                   out, 4096, sO, nullptr, 0, nullptr, 0, 4096);
}

// round 13
// speedup vs baseline: 1.5264x; 1.0204x over previous
#include <cuda_runtime.h>
#include <cuda_fp16.h>
#include <cstdint>
#include <cstddef>

// ---------------------------------------------------------------------------
// Sigmoid attention, algebraically refactored (R8-R11) + R13 (= R12 resubmit;
// R12 bench was an infra container failure, no kernel signal):
//   s[n,m] = y_n·x_m + u·x_m + w·x_n + c0,  y = x·(Wq^T Wk)  (O_CH contracts early)
// Pipeline (D[m,n] = sum_k A[m,k]*B[n,k], K-contiguous fp16, fp32 acc):
//   Mkq = Wk^T·Wq (512x512) ; ONE launch: {y = xT·Mkq ; v = Wv·xT + bv ; rb/cb}
//   aT[m,n] = sigmoid(x_m·y_n + rb[m] + cb[n])   (K=512)
//   out = v·aT  (K=4096)
// R12/13: rbcb folded into gemm_dual as z=8 slice (hides under tensor work);
//      uw reads coalesced fp16 WqT/WkT rows. Hot GEMM mainloop unchanged
//      (128x128 CTA, 4 warps of 64x64, 3-stage cp.async, ldmatrix.x4
//      double-buffered fragments, 2 CTA/SM).
// ---------------------------------------------------------------------------

#define BM 128
#define BN 128
#define STAGE 32768               // A tile 16KB + B tile 16KB
#define NSTAGE 3
#define SMEM_TOTAL (NSTAGE * STAGE)

// ------------------------------- scratch ------------------------------------
#define AL16 __align__(16)
static __device__ AL16 __half g_xT [(size_t)4*4096*512];    // xT[b][n][c]
static __device__ AL16 __half g_WqT[512*1024];              // Wq^T[c][o] (o pad 1000->1024)
static __device__ AL16 __half g_WkT[512*1024];              // Wk^T[c][o]
static __device__ AL16 __half g_Wv [512*512];               // Wv[c][c'] fp16
static __device__ AL16 __half g_M  [512*512];               // Mkq = Wk^T·Wq
static __device__ AL16 __half g_y  [(size_t)4*4096*512];    // y[b][n][c']
static __device__ AL16 __half g_v  [(size_t)4*512*4096];    // v[b][c][n]
static __device__ AL16 __half g_a  [(size_t)4*4096*4096];   // aT[b][m][n]
static __device__ float g_bv[512];
static __device__ float g_u[512], g_w[512], g_c0[1];
static __device__ float g_rb[4*4096], g_cb[4*4096];         // row/col bias for alpha

// ------------------------------- helpers ------------------------------------
__device__ __forceinline__ void ldsm_x4(uint32_t& r0, uint32_t& r1, uint32_t& r2, uint32_t& r3,
                                        uint32_t addr) {
    asm volatile("ldmatrix.sync.aligned.m8n8.x4.shared.b16 {%0,%1,%2,%3}, [%4];"
                 : "=r"(r0), "=r"(r1), "=r"(r2), "=r"(r3) : "r"(addr));
}

__device__ __forceinline__ void mma_fp16(float* d, const uint32_t* a, const uint32_t* b) {
    asm volatile(
        "mma.sync.aligned.m16n8k16.row.col.f32.f16.f16.f32 "
        "{%0,%1,%2,%3}, {%4,%5,%6,%7}, {%8,%9}, {%0,%1,%2,%3};\n"
        : "+f"(d[0]), "+f"(d[1]), "+f"(d[2]), "+f"(d[3])
        : "r"(a[0]), "r"(a[1]), "r"(a[2]), "r"(a[3]), "r"(b[0]), "r"(b[1]));
}

__device__ __forceinline__ float sigmoid_fast(float x) {
    float t;
    asm("tanh.approx.f32 %0, %1;" : "=f"(t) : "f"(0.5f * x));
    return 0.5f + 0.5f * t;
}

// ---------------------------- prep kernels ----------------------------------
// x[b][c][n] fp32 -> xT[b][n][c] fp16
__global__ void xpose_h(const float* __restrict__ x, __half* __restrict__ xT) {
    __shared__ float t[32][33];
    const int b = blockIdx.z;
    const float* xb = x + (size_t)b * 512 * 4096;
    const int n0 = blockIdx.x * 32, c0 = blockIdx.y * 32;
    const int tx = threadIdx.x, ty0 = threadIdx.y;
#pragma unroll
    for (int i = 0; i < 4; i++) {
        int ty = ty0 + i * 8;
        t[ty][tx] = xb[(size_t)(c0 + ty) * 4096 + n0 + tx];
    }
    __syncthreads();
    const size_t ob = (size_t)b * 4096 * 512;
#pragma unroll
    for (int i = 0; i < 4; i++) {
        int ty = ty0 + i * 8;
        xT[ob + (size_t)(n0 + ty) * 512 + c0 + tx] = __float2half_rn(t[tx][ty]);
    }
}

// merged weight prep: z=0 -> Wq^T, z=1 -> Wk^T, z=2 -> Wv fp16 + bv copy
__global__ void prep_weights(const float* __restrict__ Wq, const float* __restrict__ Wk,
                             const float* __restrict__ Wv, const float* __restrict__ bv,
                             __half* __restrict__ WqT, __half* __restrict__ WkT,
                             __half* __restrict__ Wvh, float* __restrict__ bvp) {
    const int z = blockIdx.z;
    if (z < 2) {
        __shared__ float t[32][33];
        const float* W = z ? Wk : Wq;
        __half* WT = z ? WkT : WqT;
        const int r0 = blockIdx.x * 32, c0 = blockIdx.y * 32;
        const int tx = threadIdx.x, ty0 = threadIdx.y;
#pragma unroll
        for (int i = 0; i < 4; i++) {
            int ty = ty0 + i * 8;
            int r = r0 + ty;
            t[ty][tx] = (r < 1000) ? W[(size_t)r * 512 + c0 + tx] : 0.0f;
        }
        __syncthreads();
#pragma unroll
        for (int i = 0; i < 4; i++) {
            int ty = ty0 + i * 8;
            WT[(size_t)(c0 + ty) * 1024 + r0 + tx] = __float2half_rn(t[tx][ty]);
        }
    } else {
        // 512 blocks x 256 threads x 2 elements = 262144 = full Wv coverage
        int idx = (blockIdx.y * 32 + blockIdx.x) * 256 + threadIdx.y * 32 + threadIdx.x;
        Wvh[idx]          = __float2half_rn(Wv[idx]);
        Wvh[idx + 131072] = __float2half_rn(Wv[idx + 131072]);
        if (idx < 512) bvp[idx] = bv[idx];
    }
}

// u[c] = sum_o WkT[c][o]*bq[o], w[c] = sum_o WqT[c][o]*bk[o], c0 = bq.bk
// Coalesced: WqT/WkT rows are o-contiguous fp16. Warp per channel.
__global__ void uw_kernel(const __half* __restrict__ WqT, const __half* __restrict__ WkT,
                          const float* __restrict__ bq, const float* __restrict__ bk,
                          float* __restrict__ u, float* __restrict__ w, float* __restrict__ c0) {
    const int lane = threadIdx.x & 31;
    if (blockIdx.x == 64) {
        if ((threadIdx.x >> 5) == 0) {
            float s = 0.f;
            for (int o = lane; o < 1000; o += 32) s += bq[o] * bk[o];
#pragma unroll
            for (int off = 16; off > 0; off >>= 1) s += __shfl_xor_sync(0xFFFFFFFF, s, off);
            if (lane == 0) *c0 = s;
        }
        return;
    }
    const int c = blockIdx.x * 8 + (threadIdx.x >> 5);
    const __half* kr = WkT + (size_t)c * 1024;
    const __half* qr = WqT + (size_t)c * 1024;
    float au = 0.f, aw = 0.f;
    for (int o = lane; o < 1000; o += 32) {
        au += __half2float(kr[o]) * bq[o];
        aw += __half2float(qr[o]) * bk[o];
    }
#pragma unroll
    for (int off = 16; off > 0; off >>= 1) {
        au += __shfl_xor_sync(0xFFFFFFFF, au, off);
        aw += __shfl_xor_sync(0xFFFFFFFF, aw, off);
    }
    if (lane == 0) { u[c] = au; w[c] = aw; }
}

// ------------------------- GEMM mainloop (macro body) ------------------------
#define GEMM_BODY(A_, lda_, B_, ldb_, K_)                                           \
    extern __shared__ __align__(1024) char smem[];                                  \
    const uint32_t sb = (uint32_t)__cvta_generic_to_shared(smem);                   \
    const int tid  = threadIdx.x;                                                   \
    const int lane = tid & 31;                                                      \
    const int w    = tid >> 5;                                                      \
    const int wm   = (w & 1) * 64;                                                  \
    const int wn   = (w >> 1) * 64;                                                 \
    const int g    = lane >> 2;                                                     \
    const int tg   = lane & 3;                                                      \
    const int T = (K_) / 64;                                                        \
    auto load_stage = [&](int t, int s) {                                           \
        const uint32_t st = sb + (uint32_t)(s * STAGE);                             \
        const int kc = t * 64;                                                      \
_Pragma("unroll")                                                                   \
        for (int i = 0; i < 16; i++) {                                              \
            int idx = tid + i * 128;                                                \
            int isB = idx >> 10;                                                    \
            int r   = (idx & 1023) >> 3;                                            \
            int c   = idx & 7;                                                      \
            uint32_t dst = st + (uint32_t)(isB * 16384 + r * 128 + ((c ^ (r & 7)) << 4)); \
            const __half* gp = (isB ? (B_) + (size_t)(n0 + r) * (ldb_)              \
                                    : (A_) + (size_t)(m0 + r) * (lda_)) + kc + c * 8; \
            asm volatile("cp.async.cg.shared.global [%0], [%1], 16;" :: "r"(dst), "l"(gp) : "memory"); \
        }                                                                           \
        asm volatile("cp.async.commit_group;" ::: "memory");                        \
    };                                                                              \
    float acc[4][8][4];                                                             \
_Pragma("unroll")                                                                   \
    for (int i = 0; i < 4; i++)                                                     \
_Pragma("unroll")                                                                   \
        for (int j = 0; j < 8; j++)                                                 \
_Pragma("unroll")                                                                   \
            for (int r = 0; r < 4; r++) acc[i][j][r] = 0.0f;                        \
    load_stage(0, 0);                                                               \
    load_stage(1, 1);                                                               \
    const int rowA = wm + (lane & 15);                                              \
    const int hiA  = lane >> 4;                                                     \
    const int rowB = wn + ((lane >> 4) << 3) + (lane & 7);                          \
    const int hiB  = (lane >> 3) & 1;                                               \
    for (int t = 0; t < T; t++) {                                                   \
        asm volatile("cp.async.wait_group 1;" ::: "memory");                        \
        __syncthreads();                                                            \
        const uint32_t st  = sb + (uint32_t)((t % NSTAGE) * STAGE);                 \
        const uint32_t stB = st + 16384;                                            \
        uint32_t af[2][4][4], bf[2][8][2];                                          \
        auto load_frags = [&](int ks, int buf) {                                    \
_Pragma("unroll")                                                                   \
            for (int im = 0; im < 4; im++) {                                        \
                const int r = rowA + im * 16;                                       \
                const int c = (ks * 2 + hiA) ^ (r & 7);                             \
                ldsm_x4(af[buf][im][0], af[buf][im][1], af[buf][im][2], af[buf][im][3], \
                        st + (uint32_t)(r * 128 + (c << 4)));                       \
            }                                                                       \
_Pragma("unroll")                                                                   \
            for (int jn = 0; jn < 4; jn++) {                                        \
                const int r = rowB + jn * 16;                                       \
                const int c = (ks * 2 + hiB) ^ (r & 7);                             \
                ldsm_x4(bf[buf][2*jn][0], bf[buf][2*jn][1], bf[buf][2*jn+1][0], bf[buf][2*jn+1][1], \
                        stB + (uint32_t)(r * 128 + (c << 4)));                      \
            }                                                                       \
        };                                                                          \
        load_frags(0, 0);                                                           \
        if (t + 2 < T) load_stage(t + 2, (t + 2) % NSTAGE);                         \
_Pragma("unroll")                                                                   \
        for (int ks = 0; ks < 4; ks++) {                                            \
            const int cur = ks & 1;                                                 \
            if (ks < 3) load_frags(ks + 1, cur ^ 1);                                \
_Pragma("unroll")                                                                   \
            for (int im = 0; im < 4; im++)                                          \
_Pragma("unroll")                                                                   \
                for (int in = 0; in < 8; in++)                                      \
                    mma_fp16(acc[im][in], af[cur][im], bf[cur][in]);                \
        }                                                                           \
    }

// ---------------------- hot GEMM (templated epilogue) ------------------------
// EPI: 0 = fp32 store (out) ; 1 = fp16 store (M) ; 3 = sigmoid+biases (alpha)
template <int EPI>
__global__ __launch_bounds__(128, 2)
void gemm_h(const __half* __restrict__ Ag, int lda, size_t sA,
            const __half* __restrict__ Bg, int ldb, size_t sB,
            void* Dg, int ldd, size_t sD,
            const float* __restrict__ bias1, int s1,
            const float* __restrict__ bias2, int s2,
            int K) {
    const __half* A = Ag + (size_t)blockIdx.z * sA;
    const __half* B = Bg + (size_t)blockIdx.z * sB;
    const float* b1 = (EPI == 3) ? bias1 + (size_t)blockIdx.z * s1 : nullptr;
    const float* b2 = (EPI == 3) ? bias2 + (size_t)blockIdx.z * s2 : nullptr;
    const int m0 = blockIdx.y * BM;
    const int n0 = blockIdx.x * BN;

    GEMM_BODY(A, lda, B, ldb, K)

#pragma unroll
    for (int im = 0; im < 4; im++) {
        const int r0 = m0 + wm + im * 16 + g;
#pragma unroll
        for (int in = 0; in < 8; in++) {
            const int c = n0 + wn + in * 8 + 2 * tg;
#pragma unroll
            for (int h = 0; h < 2; h++) {
                const int r = r0 + h * 8;
                float vx = acc[im][in][2 * h];
                float vy = acc[im][in][2 * h + 1];
                if (EPI == 3) {
                    float bb = b1[r];
                    vx = sigmoid_fast(vx + bb + b2[c]);
                    vy = sigmoid_fast(vy + bb + b2[c + 1]);
                }
                if (EPI == 0) {
                    float* D = (float*)Dg + (size_t)blockIdx.z * sD + (size_t)r * ldd + c;
                    *reinterpret_cast<float2*>(D) = make_float2(vx, vy);
                } else {
                    __half* D = (__half*)Dg + (size_t)blockIdx.z * sD + (size_t)r * ldd + c;
                    *reinterpret_cast<__half2*>(D) = __floats2half2_rn(vx, vy);
                }
            }
        }
    }
}

// --------- merged v/y GEMM + rb/cb slice: one launch, runtime select ---------
// grid (128, 1, 9): z<4 -> v GEMM batch z; z in [4,8) -> y GEMM batch z-4;
//                   z==8 -> rb/cb computation (hidden under the GEMM slices).
__global__ __launch_bounds__(128, 2)
void gemm_dual(const __half* __restrict__ Wvh, const __half* __restrict__ xT,
               const __half* __restrict__ Mkq,
               __half* __restrict__ v, __half* __restrict__ y,
               const float* __restrict__ bvp,
               const float* __restrict__ u_, const float* __restrict__ w_,
               const float* __restrict__ c0_,
               float* __restrict__ rb, float* __restrict__ cb) {
    const size_t sXT = (size_t)4096 * 512;
    const int z = blockIdx.z;

    if (z == 8) {
        // rb[row] = u.x_row ; cb[row] = w.x_row + c0 ; 128 blocks x 128 rows
        extern __shared__ __align__(1024) float smemf[];
        float* su = smemf;            // 512 floats
        float* sw = smemf + 512;      // 512 floats
        const int tid = threadIdx.x;
        for (int i = tid; i < 512; i += 128) { su[i] = u_[i]; sw[i] = w_[i]; }
        __syncthreads();
        const float cc0 = *c0_;
        const int lane = tid & 31;
        const int warp = tid >> 5;
        for (int i = 0; i < 32; i++) {
            const int row = blockIdx.x * 128 + warp * 32 + i;
            const uint4* xr = reinterpret_cast<const uint4*>(xT + (size_t)row * 512);
            float au = 0.f, aw = 0.f;
#pragma unroll
            for (int j = 0; j < 2; j++) {
                const int v4 = lane + j * 32;          // uint4 index, 64 per row
                uint4 p = xr[v4];
                const __half2* h2 = reinterpret_cast<const __half2*>(&p);
                const int base = v4 * 8;
#pragma unroll
                for (int q = 0; q < 4; q++) {
                    float2 f = __half22float2(h2[q]);
                    au += su[base + 2*q] * f.x + su[base + 2*q + 1] * f.y;
                    aw += sw[base + 2*q] * f.x + sw[base + 2*q + 1] * f.y;
                }
            }
#pragma unroll
            for (int off = 16; off > 0; off >>= 1) {
                au += __shfl_xor_sync(0xFFFFFFFF, au, off);
                aw += __shfl_xor_sync(0xFFFFFFFF, aw, off);
            }
            if (lane == 0) { rb[row] = au; cb[row] = aw + cc0; }
        }
        return;
    }

    const int isV = (z < 4);
    const int b = isV ? z : z - 4;
    const int id = blockIdx.x;

    const __half* A;  const __half* B;  __half* D;
    int lda, ldb, ldd, m0, n0;
    const float* b1 = nullptr;
    if (isV) {         // v[c][n'] = Wv·xT + bv : M=512, N=4096, K=512; grid 4m x 32n
        A = Wvh; lda = 512;
        B = xT + (size_t)b * sXT; ldb = 512;
        D = v + (size_t)b * ((size_t)512 * 4096); ldd = 4096;
        m0 = (id >> 5) * BM;  n0 = (id & 31) * BN;
        b1 = bvp;
    } else {           // y[n][c'] = xT·Mkq : M=4096, N=512, K=512; grid 32m x 4n
        A = xT + (size_t)b * sXT; lda = 512;
        B = Mkq; ldb = 512;
        D = y + (size_t)b * sXT; ldd = 512;
        m0 = (id >> 2) * BM;  n0 = (id & 3) * BN;
    }

    GEMM_BODY(A, lda, B, ldb, 512)

#pragma unroll
    for (int im = 0; im < 4; im++) {
        const int r0 = m0 + wm + im * 16 + g;
#pragma unroll
        for (int in = 0; in < 8; in++) {
            const int c = n0 + wn + in * 8 + 2 * tg;
#pragma unroll
            for (int h = 0; h < 2; h++) {
                const int r = r0 + h * 8;
                float vx = acc[im][in][2 * h];
                float vy = acc[im][in][2 * h + 1];
                if (isV) { float bb = b1[r]; vx += bb; vy += bb; }
                __half* Dp = D + (size_t)r * ldd + c;
                *reinterpret_cast<__half2*>(Dp) = __floats2half2_rn(vx, vy);
            }
        }
    }
}

// ------------------------------- launch -------------------------------------
extern "C" void kernel_launch(void* const* d_in, const int* in_sizes, int n_in,
                              void* d_out, int out_size) {
    (void)in_sizes; (void)n_in; (void)out_size;
    const float* x  = (const float*)d_in[0];
    const float* Wq = (const float*)d_in[1];
    const float* bq = (const float*)d_in[2];
    const float* Wk = (const float*)d_in[3];
    const float* bk = (const float*)d_in[4];
    const float* Wv = (const float*)d_in[5];
    const float* bv = (const float*)d_in[6];
    float* out = (float*)d_out;

    __half *xT,*WqT,*WkT,*Wvh,*M,*y,*v,*a;
    float *bvp,*u,*w,*c0,*rb,*cb;
    cudaGetSymbolAddress((void**)&xT,  g_xT);
    cudaGetSymbolAddress((void**)&WqT, g_WqT);
    cudaGetSymbolAddress((void**)&WkT, g_WkT);
    cudaGetSymbolAddress((void**)&Wvh, g_Wv);
    cudaGetSymbolAddress((void**)&M,   g_M);
    cudaGetSymbolAddress((void**)&y,   g_y);
    cudaGetSymbolAddress((void**)&v,   g_v);
    cudaGetSymbolAddress((void**)&a,   g_a);
    cudaGetSymbolAddress((void**)&bvp, g_bv);
    cudaGetSymbolAddress((void**)&u,   g_u);
    cudaGetSymbolAddress((void**)&w,   g_w);
    cudaGetSymbolAddress((void**)&c0,  g_c0);
    cudaGetSymbolAddress((void**)&rb,  g_rb);
    cudaGetSymbolAddress((void**)&cb,  g_cb);

    cudaFuncSetAttribute(gemm_h<0>, cudaFuncAttributeMaxDynamicSharedMemorySize, SMEM_TOTAL);
    cudaFuncSetAttribute(gemm_h<1>, cudaFuncAttributeMaxDynamicSharedMemorySize, SMEM_TOTAL);
    cudaFuncSetAttribute(gemm_h<3>, cudaFuncAttributeMaxDynamicSharedMemorySize, SMEM_TOTAL);
    cudaFuncSetAttribute(gemm_dual, cudaFuncAttributeMaxDynamicSharedMemorySize, SMEM_TOTAL);

    // ---- prep ----
    prep_weights<<<dim3(32, 16, 3), dim3(32, 8)>>>(Wq, Wk, Wv, bv, WqT, WkT, Wvh, bvp);
    xpose_h<<<dim3(128, 16, 4), dim3(32, 8)>>>(x, xT);
    uw_kernel<<<65, 256>>>(WqT, WkT, bq, bk, u, w, c0);

    const size_t sXT = (size_t)4096 * 512;
    const size_t sV  = (size_t)512 * 4096;
    const size_t sAL = (size_t)4096 * 4096;
    const size_t sO  = (size_t)512 * 4096;

    // Mkq = Wk^T·Wq  (M=512,N=512,K=1024)
    gemm_h<1><<<dim3(4, 4, 1), 128, SMEM_TOTAL>>>(WkT, 1024, 0, WqT, 1024, 0,
                                                  M, 512, 0, nullptr, 0, nullptr, 0, 1024);
    // merged: v = Wv·xT + bv, y = xT·Mkq, rb/cb  (one 1152-CTA launch)
    gemm_dual<<<dim3(128, 1, 9), 128, SMEM_TOTAL>>>(Wvh, xT, M, v, y, bvp, u, w, c0, rb, cb);
    // aT[m][n] = sigmoid(x_m·y_n + rb[m] + cb[n])  (M=N=4096,K=512)
    gemm_h<3><<<dim3(32, 32, 4), 128, SMEM_TOTAL>>>(xT, 512, sXT, y, 512, sXT,
                                                    a, 4096, sAL, rb, 4096, cb, 4096, 512);
    // out[c][m] = v·aT  (M=512,N=4096,K=4096) fp32
    gemm_h<0><<<dim3(32, 4, 4), 128, SMEM_TOTAL>>>(v, 4096, sV, a, 4096, sAL,
                                                   out, 4096, sO, nullptr, 0, nullptr, 0, 4096);
}

// round 14
// speedup vs baseline: 1.5726x; 1.0302x over previous
#include <cuda_runtime.h>
#include <cuda_fp16.h>
#include <cstdint>
#include <cstddef>

// ---------------------------------------------------------------------------
// Sigmoid attention, algebraically refactored (R8-R13) + R14 split-K M GEMM:
//   s[n,m] = y_n·x_m + u·x_m + w·x_n + c0,  y = x·(Wq^T Wk)  (O_CH contracts early)
// Pipeline (D[m,n] = sum_k A[m,k]*B[n,k], K-contiguous fp16, fp32 acc):
//   Mpart[z] = Wk^T·Wq over K-chunk z (split-K x4, 64 CTAs via gemm_h<0> with
//              batch-stride abused as K-offset) ; reduce folded into uw launch
//   ONE launch: {y = xT·Mkq ; v = Wv·xT + bv ; rb/cb}
//   aT[m,n] = sigmoid(x_m·y_n + rb[m] + cb[n])   (K=512)
//   out = v·aT  (K=4096)
// Hot GEMM mainloop unchanged (128x128 CTA, 4 warps of 64x64, 3-stage
// cp.async, ldmatrix.x4 double-buffered fragments, 2 CTA/SM).
// ---------------------------------------------------------------------------

#define BM 128
#define BN 128
#define STAGE 32768               // A tile 16KB + B tile 16KB
#define NSTAGE 3
#define SMEM_TOTAL (NSTAGE * STAGE)

// ------------------------------- scratch ------------------------------------
#define AL16 __align__(16)
static __device__ AL16 __half g_xT [(size_t)4*4096*512];    // xT[b][n][c]
static __device__ AL16 __half g_WqT[512*1024];              // Wq^T[c][o] (o pad 1000->1024)
static __device__ AL16 __half g_WkT[512*1024];              // Wk^T[c][o]
static __device__ AL16 __half g_Wv [512*512];               // Wv[c][c'] fp16
static __device__ AL16 float  g_Mp [4*512*512];             // split-K partials (fp32)
static __device__ AL16 __half g_M  [512*512];               // Mkq = Wk^T·Wq
static __device__ AL16 __half g_y  [(size_t)4*4096*512];    // y[b][n][c']
static __device__ AL16 __half g_v  [(size_t)4*512*4096];    // v[b][c][n]
static __device__ AL16 __half g_a  [(size_t)4*4096*4096];   // aT[b][m][n]
static __device__ float g_bv[512];
static __device__ float g_u[512], g_w[512], g_c0[1];
static __device__ float g_rb[4*4096], g_cb[4*4096];         // row/col bias for alpha

// ------------------------------- helpers ------------------------------------
__device__ __forceinline__ void ldsm_x4(uint32_t& r0, uint32_t& r1, uint32_t& r2, uint32_t& r3,
                                        uint32_t addr) {
    asm volatile("ldmatrix.sync.aligned.m8n8.x4.shared.b16 {%0,%1,%2,%3}, [%4];"
                 : "=r"(r0), "=r"(r1), "=r"(r2), "=r"(r3) : "r"(addr));
}

__device__ __forceinline__ void mma_fp16(float* d, const uint32_t* a, const uint32_t* b) {
    asm volatile(
        "mma.sync.aligned.m16n8k16.row.col.f32.f16.f16.f32 "
        "{%0,%1,%2,%3}, {%4,%5,%6,%7}, {%8,%9}, {%0,%1,%2,%3};\n"
        : "+f"(d[0]), "+f"(d[1]), "+f"(d[2]), "+f"(d[3])
        : "r"(a[0]), "r"(a[1]), "r"(a[2]), "r"(a[3]), "r"(b[0]), "r"(b[1]));
}

__device__ __forceinline__ float sigmoid_fast(float x) {
    float t;
    asm("tanh.approx.f32 %0, %1;" : "=f"(t) : "f"(0.5f * x));
    return 0.5f + 0.5f * t;
}

// ---------------------------- prep kernels ----------------------------------
// x[b][c][n] fp32 -> xT[b][n][c] fp16
__global__ void xpose_h(const float* __restrict__ x, __half* __restrict__ xT) {
    __shared__ float t[32][33];
    const int b = blockIdx.z;
    const float* xb = x + (size_t)b * 512 * 4096;
    const int n0 = blockIdx.x * 32, c0 = blockIdx.y * 32;
    const int tx = threadIdx.x, ty0 = threadIdx.y;
#pragma unroll
    for (int i = 0; i < 4; i++) {
        int ty = ty0 + i * 8;
        t[ty][tx] = xb[(size_t)(c0 + ty) * 4096 + n0 + tx];
    }
    __syncthreads();
    const size_t ob = (size_t)b * 4096 * 512;
#pragma unroll
    for (int i = 0; i < 4; i++) {
        int ty = ty0 + i * 8;
        xT[ob + (size_t)(n0 + ty) * 512 + c0 + tx] = __float2half_rn(t[tx][ty]);
    }
}

// merged weight prep: z=0 -> Wq^T, z=1 -> Wk^T, z=2 -> Wv fp16 + bv copy
__global__ void prep_weights(const float* __restrict__ Wq, const float* __restrict__ Wk,
                             const float* __restrict__ Wv, const float* __restrict__ bv,
                             __half* __restrict__ WqT, __half* __restrict__ WkT,
                             __half* __restrict__ Wvh, float* __restrict__ bvp) {
    const int z = blockIdx.z;
    if (z < 2) {
        __shared__ float t[32][33];
        const float* W = z ? Wk : Wq;
        __half* WT = z ? WkT : WqT;
        const int r0 = blockIdx.x * 32, c0 = blockIdx.y * 32;
        const int tx = threadIdx.x, ty0 = threadIdx.y;
#pragma unroll
        for (int i = 0; i < 4; i++) {
            int ty = ty0 + i * 8;
            int r = r0 + ty;
            t[ty][tx] = (r < 1000) ? W[(size_t)r * 512 + c0 + tx] : 0.0f;
        }
        __syncthreads();
#pragma unroll
        for (int i = 0; i < 4; i++) {
            int ty = ty0 + i * 8;
            WT[(size_t)(c0 + ty) * 1024 + r0 + tx] = __float2half_rn(t[tx][ty]);
        }
    } else {
        // 512 blocks x 256 threads x 2 elements = 262144 = full Wv coverage
        int idx = (blockIdx.y * 32 + blockIdx.x) * 256 + threadIdx.y * 32 + threadIdx.x;
        Wvh[idx]          = __float2half_rn(Wv[idx]);
        Wvh[idx + 131072] = __float2half_rn(Wv[idx + 131072]);
        if (idx < 512) bvp[idx] = bv[idx];
    }
}

// Blocks 0-63: u[c], w[c] (warp per channel, coalesced fp16 rows).
// Block 64:   c0 = bq.bk.
// Blocks 65-320: reduce 4 split-K fp32 partials -> fp16 M (float4, 4 elems/thr).
__global__ void uw_reduce_kernel(const __half* __restrict__ WqT, const __half* __restrict__ WkT,
                                 const float* __restrict__ bq, const float* __restrict__ bk,
                                 const float* __restrict__ Mp, __half* __restrict__ M,
                                 float* __restrict__ u, float* __restrict__ w,
                                 float* __restrict__ c0) {
    const int lane = threadIdx.x & 31;
    if (blockIdx.x >= 65) {
        const int base = (blockIdx.x - 65) * 1024 + threadIdx.x * 4;   // 256 blks x 256 thr x 4
        float4 s = *reinterpret_cast<const float4*>(Mp + base);
#pragma unroll
        for (int p = 1; p < 4; p++) {
            float4 t = *reinterpret_cast<const float4*>(Mp + p * 262144 + base);
            s.x += t.x; s.y += t.y; s.z += t.z; s.w += t.w;
        }
        __half2 h0 = __floats2half2_rn(s.x, s.y);
        __half2 h1 = __floats2half2_rn(s.z, s.w);
        *reinterpret_cast<uint2*>(M + base) =
            make_uint2(*reinterpret_cast<uint32_t*>(&h0), *reinterpret_cast<uint32_t*>(&h1));
        return;
    }
    if (blockIdx.x == 64) {
        if ((threadIdx.x >> 5) == 0) {
            float s = 0.f;
            for (int o = lane; o < 1000; o += 32) s += bq[o] * bk[o];
#pragma unroll
            for (int off = 16; off > 0; off >>= 1) s += __shfl_xor_sync(0xFFFFFFFF, s, off);
            if (lane == 0) *c0 = s;
        }
        return;
    }
    const int c = blockIdx.x * 8 + (threadIdx.x >> 5);
    const __half* kr = WkT + (size_t)c * 1024;
    const __half* qr = WqT + (size_t)c * 1024;
    float au = 0.f, aw = 0.f;
    for (int o = lane; o < 1000; o += 32) {
        au += __half2float(kr[o]) * bq[o];
        aw += __half2float(qr[o]) * bk[o];
    }
#pragma unroll
    for (int off = 16; off > 0; off >>= 1) {
        au += __shfl_xor_sync(0xFFFFFFFF, au, off);
        aw += __shfl_xor_sync(0xFFFFFFFF, aw, off);
    }
    if (lane == 0) { u[c] = au; w[c] = aw; }
}

// ------------------------- GEMM mainloop (macro body) ------------------------
#define GEMM_BODY(A_, lda_, B_, ldb_, K_)                                           \
    extern __shared__ __align__(1024) char smem[];                                  \
    const uint32_t sb = (uint32_t)__cvta_generic_to_shared(smem);                   \
    const int tid  = threadIdx.x;                                                   \
    const int lane = tid & 31;                                                      \
    const int w    = tid >> 5;                                                      \
    const int wm   = (w & 1) * 64;                                                  \
    const int wn   = (w >> 1) * 64;                                                 \
    const int g    = lane >> 2;                                                     \
    const int tg   = lane & 3;                                                      \
    const int T = (K_) / 64;                                                        \
    auto load_stage = [&](int t, int s) {                                           \
        const uint32_t st = sb + (uint32_t)(s * STAGE);                             \
        const int kc = t * 64;                                                      \
_Pragma("unroll")                                                                   \
        for (int i = 0; i < 16; i++) {                                              \
            int idx = tid + i * 128;                                                \
            int isB = idx >> 10;                                                    \
            int r   = (idx & 1023) >> 3;                                            \
            int c   = idx & 7;                                                      \
            uint32_t dst = st + (uint32_t)(isB * 16384 + r * 128 + ((c ^ (r & 7)) << 4)); \
            const __half* gp = (isB ? (B_) + (size_t)(n0 + r) * (ldb_)              \
                                    : (A_) + (size_t)(m0 + r) * (lda_)) + kc + c * 8; \
            asm volatile("cp.async.cg.shared.global [%0], [%1], 16;" :: "r"(dst), "l"(gp) : "memory"); \
        }                                                                           \
        asm volatile("cp.async.commit_group;" ::: "memory");                        \
    };                                                                              \
    float acc[4][8][4];                                                             \
_Pragma("unroll")                                                                   \
    for (int i = 0; i < 4; i++)                                                     \
_Pragma("unroll")                                                                   \
        for (int j = 0; j < 8; j++)                                                 \
_Pragma("unroll")                                                                   \
            for (int r = 0; r < 4; r++) acc[i][j][r] = 0.0f;                        \
    load_stage(0, 0);                                                               \
    load_stage(1, 1);                                                               \
    const int rowA = wm + (lane & 15);                                              \
    const int hiA  = lane >> 4;                                                     \
    const int rowB = wn + ((lane >> 4) << 3) + (lane & 7);                          \
    const int hiB  = (lane >> 3) & 1;                                               \
    for (int t = 0; t < T; t++) {                                                   \
        asm volatile("cp.async.wait_group 1;" ::: "memory");                        \
        __syncthreads();                                                            \
        const uint32_t st  = sb + (uint32_t)((t % NSTAGE) * STAGE);                 \
        const uint32_t stB = st + 16384;                                            \
        uint32_t af[2][4][4], bf[2][8][2];                                          \
        auto load_frags = [&](int ks, int buf) {                                    \
_Pragma("unroll")                                                                   \
            for (int im = 0; im < 4; im++) {                                        \
                const int r = rowA + im * 16;                                       \
                const int c = (ks * 2 + hiA) ^ (r & 7);                             \
                ldsm_x4(af[buf][im][0], af[buf][im][1], af[buf][im][2], af[buf][im][3], \
                        st + (uint32_t)(r * 128 + (c << 4)));                       \
            }                                                                       \
_Pragma("unroll")                                                                   \
            for (int jn = 0; jn < 4; jn++) {                                        \
                const int r = rowB + jn * 16;                                       \
                const int c = (ks * 2 + hiB) ^ (r & 7);                             \
                ldsm_x4(bf[buf][2*jn][0], bf[buf][2*jn][1], bf[buf][2*jn+1][0], bf[buf][2*jn+1][1], \
                        stB + (uint32_t)(r * 128 + (c << 4)));                      \
            }                                                                       \
        };                                                                          \
        load_frags(0, 0);                                                           \
        if (t + 2 < T) load_stage(t + 2, (t + 2) % NSTAGE);                         \
_Pragma("unroll")                                                                   \
        for (int ks = 0; ks < 4; ks++) {                                            \
            const int cur = ks & 1;                                                 \
            if (ks < 3) load_frags(ks + 1, cur ^ 1);                                \
_Pragma("unroll")                                                                   \
            for (int im = 0; im < 4; im++)                                          \
_Pragma("unroll")                                                                   \
                for (int in = 0; in < 8; in++)                                      \
                    mma_fp16(acc[im][in], af[cur][im], bf[cur][in]);                \
        }                                                                           \
    }

// ---------------------- hot GEMM (templated epilogue) ------------------------
// EPI: 0 = fp32 store (out / M split-K partials) ; 3 = sigmoid+biases (alpha)
template <int EPI>
__global__ __launch_bounds__(128, 2)
void gemm_h(const __half* __restrict__ Ag, int lda, size_t sA,
            const __half* __restrict__ Bg, int ldb, size_t sB,
            void* Dg, int ldd, size_t sD,
            const float* __restrict__ bias1, int s1,
            const float* __restrict__ bias2, int s2,
            int K) {
    const __half* A = Ag + (size_t)blockIdx.z * sA;
    const __half* B = Bg + (size_t)blockIdx.z * sB;
    const float* b1 = (EPI == 3) ? bias1 + (size_t)blockIdx.z * s1 : nullptr;
    const float* b2 = (EPI == 3) ? bias2 + (size_t)blockIdx.z * s2 : nullptr;
    const int m0 = blockIdx.y * BM;
    const int n0 = blockIdx.x * BN;

    GEMM_BODY(A, lda, B, ldb, K)

#pragma unroll
    for (int im = 0; im < 4; im++) {
        const int r0 = m0 + wm + im * 16 + g;
#pragma unroll
        for (int in = 0; in < 8; in++) {
            const int c = n0 + wn + in * 8 + 2 * tg;
#pragma unroll
            for (int h = 0; h < 2; h++) {
                const int r = r0 + h * 8;
                float vx = acc[im][in][2 * h];
                float vy = acc[im][in][2 * h + 1];
                if (EPI == 3) {
                    float bb = b1[r];
                    vx = sigmoid_fast(vx + bb + b2[c]);
                    vy = sigmoid_fast(vy + bb + b2[c + 1]);
                }
                if (EPI == 0) {
                    float* D = (float*)Dg + (size_t)blockIdx.z * sD + (size_t)r * ldd + c;
                    *reinterpret_cast<float2*>(D) = make_float2(vx, vy);
                } else {
                    __half* D = (__half*)Dg + (size_t)blockIdx.z * sD + (size_t)r * ldd + c;
                    *reinterpret_cast<__half2*>(D) = __floats2half2_rn(vx, vy);
                }
            }
        }
    }
}

// --------- merged v/y GEMM + rb/cb slice: one launch, runtime select ---------
// grid (128, 1, 9): z<4 -> v GEMM batch z; z in [4,8) -> y GEMM batch z-4;
//                   z==8 -> rb/cb computation (hidden under the GEMM slices).
__global__ __launch_bounds__(128, 2)
void gemm_dual(const __half* __restrict__ Wvh, const __half* __restrict__ xT,
               const __half* __restrict__ Mkq,
               __half* __restrict__ v, __half* __restrict__ y,
               const float* __restrict__ bvp,
               const float* __restrict__ u_, const float* __restrict__ w_,
               const float* __restrict__ c0_,
               float* __restrict__ rb, float* __restrict__ cb) {
    const size_t sXT = (size_t)4096 * 512;
    const int z = blockIdx.z;

    if (z == 8) {
        // rb[row] = u.x_row ; cb[row] = w.x_row + c0 ; 128 blocks x 128 rows
        extern __shared__ __align__(1024) float smemf[];
        float* su = smemf;            // 512 floats
        float* sw = smemf + 512;      // 512 floats
        const int tid = threadIdx.x;
        for (int i = tid; i < 512; i += 128) { su[i] = u_[i]; sw[i] = w_[i]; }
        __syncthreads();
        const float cc0 = *c0_;
        const int lane = tid & 31;
        const int warp = tid >> 5;
        for (int i = 0; i < 32; i++) {
            const int row = blockIdx.x * 128 + warp * 32 + i;
            const uint4* xr = reinterpret_cast<const uint4*>(xT + (size_t)row * 512);
            float au = 0.f, aw = 0.f;
#pragma unroll
            for (int j = 0; j < 2; j++) {
                const int v4 = lane + j * 32;          // uint4 index, 64 per row
                uint4 p = xr[v4];
                const __half2* h2 = reinterpret_cast<const __half2*>(&p);
                const int base = v4 * 8;
#pragma unroll
                for (int q = 0; q < 4; q++) {
                    float2 f = __half22float2(h2[q]);
                    au += su[base + 2*q] * f.x + su[base + 2*q + 1] * f.y;
                    aw += sw[base + 2*q] * f.x + sw[base + 2*q + 1] * f.y;
                }
            }
#pragma unroll
            for (int off = 16; off > 0; off >>= 1) {
                au += __shfl_xor_sync(0xFFFFFFFF, au, off);
                aw += __shfl_xor_sync(0xFFFFFFFF, aw, off);
            }
            if (lane == 0) { rb[row] = au; cb[row] = aw + cc0; }
        }
        return;
    }

    const int isV = (z < 4);
    const int b = isV ? z : z - 4;
    const int id = blockIdx.x;

    const __half* A;  const __half* B;  __half* D;
    int lda, ldb, ldd, m0, n0;
    const float* b1 = nullptr;
    if (isV) {         // v[c][n'] = Wv·xT + bv : M=512, N=4096, K=512; grid 4m x 32n
        A = Wvh; lda = 512;
        B = xT + (size_t)b * sXT; ldb = 512;
        D = v + (size_t)b * ((size_t)512 * 4096); ldd = 4096;
        m0 = (id >> 5) * BM;  n0 = (id & 31) * BN;
        b1 = bvp;
    } else {           // y[n][c'] = xT·Mkq : M=4096, N=512, K=512; grid 32m x 4n
        A = xT + (size_t)b * sXT; lda = 512;
        B = Mkq; ldb = 512;
        D = y + (size_t)b * sXT; ldd = 512;
        m0 = (id >> 2) * BM;  n0 = (id & 3) * BN;
    }

    GEMM_BODY(A, lda, B, ldb, 512)

#pragma unroll
    for (int im = 0; im < 4; im++) {
        const int r0 = m0 + wm + im * 16 + g;
#pragma unroll
        for (int in = 0; in < 8; in++) {
            const int c = n0 + wn + in * 8 + 2 * tg;
#pragma unroll
            for (int h = 0; h < 2; h++) {
                const int r = r0 + h * 8;
                float vx = acc[im][in][2 * h];
                float vy = acc[im][in][2 * h + 1];
                if (isV) { float bb = b1[r]; vx += bb; vy += bb; }
                __half* Dp = D + (size_t)r * ldd + c;
                *reinterpret_cast<__half2*>(Dp) = __floats2half2_rn(vx, vy);
            }
        }
    }
}

// ------------------------------- launch -------------------------------------
extern "C" void kernel_launch(void* const* d_in, const int* in_sizes, int n_in,
                              void* d_out, int out_size) {
    (void)in_sizes; (void)n_in; (void)out_size;
    const float* x  = (const float*)d_in[0];
    const float* Wq = (const float*)d_in[1];
    const float* bq = (const float*)d_in[2];
    const float* Wk = (const float*)d_in[3];
    const float* bk = (const float*)d_in[4];
    const float* Wv = (const float*)d_in[5];
    const float* bv = (const float*)d_in[6];
    float* out = (float*)d_out;

    __half *xT,*WqT,*WkT,*Wvh,*M,*y,*v,*a;
    float *Mp,*bvp,*u,*w,*c0,*rb,*cb;
    cudaGetSymbolAddress((void**)&xT,  g_xT);
    cudaGetSymbolAddress((void**)&WqT, g_WqT);
    cudaGetSymbolAddress((void**)&WkT, g_WkT);
    cudaGetSymbolAddress((void**)&Wvh, g_Wv);
    cudaGetSymbolAddress((void**)&Mp,  g_Mp);
    cudaGetSymbolAddress((void**)&M,   g_M);
    cudaGetSymbolAddress((void**)&y,   g_y);
    cudaGetSymbolAddress((void**)&v,   g_v);
    cudaGetSymbolAddress((void**)&a,   g_a);
    cudaGetSymbolAddress((void**)&bvp, g_bv);
    cudaGetSymbolAddress((void**)&u,   g_u);
    cudaGetSymbolAddress((void**)&w,   g_w);
    cudaGetSymbolAddress((void**)&c0,  g_c0);
    cudaGetSymbolAddress((void**)&rb,  g_rb);
    cudaGetSymbolAddress((void**)&cb,  g_cb);

    cudaFuncSetAttribute(gemm_h<0>, cudaFuncAttributeMaxDynamicSharedMemorySize, SMEM_TOTAL);
    cudaFuncSetAttribute(gemm_h<3>, cudaFuncAttributeMaxDynamicSharedMemorySize, SMEM_TOTAL);
    cudaFuncSetAttribute(gemm_dual, cudaFuncAttributeMaxDynamicSharedMemorySize, SMEM_TOTAL);

    // ---- prep ----
    prep_weights<<<dim3(32, 16, 3), dim3(32, 8)>>>(Wq, Wk, Wv, bv, WqT, WkT, Wvh, bvp);
    xpose_h<<<dim3(128, 16, 4), dim3(32, 8)>>>(x, xT);

    const size_t sXT = (size_t)4096 * 512;
    const size_t sV  = (size_t)512 * 4096;
    const size_t sAL = (size_t)4096 * 4096;
    const size_t sO  = (size_t)512 * 4096;

    // Mpart[z] = Wk^T·Wq over K-chunk z (split-K x4: sA/sB=256 = K offset per z)
    gemm_h<0><<<dim3(4, 4, 4), 128, SMEM_TOTAL>>>(WkT, 1024, 256, WqT, 1024, 256,
                                                  Mp, 512, 262144, nullptr, 0, nullptr, 0, 256);
    // u/w/c0 + reduce Mpart -> fp16 M   (one launch, 321 blocks)
    uw_reduce_kernel<<<321, 256>>>(WqT, WkT, bq, bk, Mp, M, u, w, c0);
    // merged: v = Wv·xT + bv, y = xT·Mkq, rb/cb  (one 1152-CTA launch)
    gemm_dual<<<dim3(128, 1, 9), 128, SMEM_TOTAL>>>(Wvh, xT, M, v, y, bvp, u, w, c0, rb, cb);
    // aT[m][n] = sigmoid(x_m·y_n + rb[m] + cb[n])  (M=N=4096,K=512)
    gemm_h<3><<<dim3(32, 32, 4), 128, SMEM_TOTAL>>>(xT, 512, sXT, y, 512, sXT,
                                                    a, 4096, sAL, rb, 4096, cb, 4096, 512);
    // out[c][m] = v·aT  (M=512,N=4096,K=4096) fp32
    gemm_h<0><<<dim3(32, 4, 4), 128, SMEM_TOTAL>>>(v, 4096, sV, a, 4096, sAL,
                                                   out, 4096, sO, nullptr, 0, nullptr, 0, 4096);
}